// round 10
// baseline (speedup 1.0000x reference)
#include <cuda_runtime.h>
#include <cuda_fp16.h>
#include <cstdint>

// Problem constants
#define NNODES 20000
#define NEDGES 200000
#define D_IN   1433
#define D_H1   1000
#define D_H2   500
#define D_OUT  7

// Padded GEMM dims
#define K1PAD  1472   // >= 1433, mult of 64
#define K2PAD  1024   // >= 1000, mult of 64
#define N1PAD  1024   // >= 1000, mult of 128
#define N2PAD  512    // >= 500,  mult of 128

// ---------------------------------------------------------------------------
// Device scratch
// ---------------------------------------------------------------------------
__device__ __align__(256) __half g_fa[(size_t)NNODES * K1PAD];
__device__ __align__(256) __half g_w1t[(size_t)N1PAD * K1PAD];
__device__ __align__(256) __half g_x1[(size_t)NNODES * K2PAD];
__device__ __align__(256) __half g_w2t[(size_t)N2PAD * K2PAD];
__device__ __align__(256) __half g_t1[(size_t)NNODES * D_H1];
__device__ __align__(256) __half g_t2[(size_t)NNODES * D_H2];
__device__ int g_count[NNODES];
__device__ int g_pos[NNODES];
__device__ int g_offs[NNODES + 1];
__device__ int g_eidx[NEDGES];

// ---------------------------------------------------------------------------
// PTX helpers
// ---------------------------------------------------------------------------
__device__ __forceinline__ uint32_t smem_to_u32(const void* p) {
    uint32_t a;
    asm("{ .reg .u64 t; cvta.to.shared.u64 t, %1; cvt.u32.u64 %0, t; }"
        : "=r"(a) : "l"(p));
    return a;
}

__device__ __forceinline__ void cp_async16(uint32_t sdst, const void* gsrc, bool ok) {
    int sz = ok ? 16 : 0;
    asm volatile("cp.async.cg.shared.global [%0], [%1], 16, %2;\n"
                 :: "r"(sdst), "l"(gsrc), "r"(sz));
}
#define CP_COMMIT() asm volatile("cp.async.commit_group;\n" ::: "memory")
#define CP_WAIT(n)  asm volatile("cp.async.wait_group %0;\n" :: "n"(n) : "memory")

__device__ __forceinline__ void ldm_x4(uint32_t& r0, uint32_t& r1, uint32_t& r2,
                                       uint32_t& r3, uint32_t addr) {
    asm volatile("ldmatrix.sync.aligned.m8n8.x4.shared.b16 {%0,%1,%2,%3}, [%4];"
                 : "=r"(r0), "=r"(r1), "=r"(r2), "=r"(r3) : "r"(addr));
}

__device__ __forceinline__ void mma_f16(float* c, const uint32_t* a, const uint32_t* b) {
    asm volatile(
        "mma.sync.aligned.m16n8k16.row.col.f32.f16.f16.f32 "
        "{%0,%1,%2,%3}, {%4,%5,%6,%7}, {%8,%9}, {%0,%1,%2,%3};"
        : "+f"(c[0]), "+f"(c[1]), "+f"(c[2]), "+f"(c[3])
        : "r"(a[0]), "r"(a[1]), "r"(a[2]), "r"(a[3]), "r"(b[0]), "r"(b[1]));
}

__device__ __forceinline__ uint32_t pack_f16x2(float a, float b) {
    __half2 h = __floats2half2_rn(a, b);
    return *reinterpret_cast<uint32_t*>(&h);
}

struct __align__(8) half4 { __half2 a, b; };

// ---------------------------------------------------------------------------
// CSR build (g_count/g_pos zeroed inside quantize_pad_kernel)
// ---------------------------------------------------------------------------
__global__ void count_kernel(const int* __restrict__ dst) {
    int e = blockIdx.x * blockDim.x + threadIdx.x;
    if (e < NEDGES) atomicAdd(&g_count[dst[e]], 1);
}
__global__ void scan_kernel() {
    __shared__ int part[1024];
    const int tid = threadIdx.x;
    const int CH = (NNODES + 1023) / 1024;
    const int base = tid * CH;
    int s = 0;
    for (int i = 0; i < CH; ++i) {
        int idx = base + i;
        if (idx < NNODES) s += g_count[idx];
    }
    part[tid] = s;
    __syncthreads();
    for (int off = 1; off < 1024; off <<= 1) {
        int v = (tid >= off) ? part[tid - off] : 0;
        __syncthreads();
        part[tid] += v;
        __syncthreads();
    }
    int run = part[tid] - s;
    for (int i = 0; i < CH; ++i) {
        int idx = base + i;
        if (idx < NNODES) { g_offs[idx] = run; run += g_count[idx]; }
    }
    if (tid == 1023) g_offs[NNODES] = part[1023];
}
__global__ void fill_kernel(const int* __restrict__ src, const int* __restrict__ dst) {
    int e = blockIdx.x * blockDim.x + threadIdx.x;
    if (e < NEDGES) {
        int d = dst[e];
        int p = atomicAdd(&g_pos[d], 1);
        g_eidx[g_offs[d] + p] = src[e];
    }
}

// ---------------------------------------------------------------------------
// Conversion: fp32 -> fp16, zero-padded; 4 elems/thread. Also zeroes CSR counters.
// ---------------------------------------------------------------------------
__global__ void quantize_pad_kernel(const float* __restrict__ src,
                                    __half* __restrict__ dstq,
                                    int M, int K, int Kpad) {
    size_t idx4 = (size_t)blockIdx.x * blockDim.x + threadIdx.x;
    if (idx4 < NNODES) { g_count[(int)idx4] = 0; g_pos[(int)idx4] = 0; }
    size_t total4 = (size_t)M * (Kpad >> 2);
    if (idx4 >= total4) return;
    int gpr = Kpad >> 2;
    int r = (int)(idx4 / gpr);
    int c = (int)(idx4 % gpr) << 2;
    float v[4];
#pragma unroll
    for (int j = 0; j < 4; ++j) {
        int cj = c + j;
        v[j] = (cj < K) ? src[(size_t)r * K + cj] : 0.f;
    }
    size_t o = (size_t)r * Kpad + c;
    *reinterpret_cast<uint2*>(dstq + o) =
        make_uint2(pack_f16x2(v[0], v[1]), pack_f16x2(v[2], v[3]));
}

// Tiled transpose: W [K,N] fp32 row-major -> Wt fp16 [Npad][Kpad], zero-padded
__global__ void transpose_f16_tiled_kernel(const float* __restrict__ W,
                                           __half* __restrict__ t,
                                           int K, int N, int Kpad, int Npad) {
    __shared__ float tile[32][33];
    const int k0 = blockIdx.x * 32;
    const int n0 = blockIdx.y * 32;
    const int tx = threadIdx.x;
    const int ty = threadIdx.y;
#pragma unroll
    for (int j = 0; j < 32; j += 8) {
        int k = k0 + ty + j, n = n0 + tx;
        tile[ty + j][tx] = (k < K && n < N) ? W[(size_t)k * N + n] : 0.f;
    }
    __syncthreads();
#pragma unroll
    for (int j = 0; j < 32; j += 8) {
        int n = n0 + ty + j, k = k0 + tx;
        if (n < Npad && k < Kpad)
            t[(size_t)n * Kpad + k] = __float2half(tile[tx][ty + j]);
    }
}

// ---------------------------------------------------------------------------
// HMMA GEMM (R7 configuration — frozen local optimum):
// CTA tile 128x128, 8 warps (4m x 2n), warp tile 32x64, 3-stage cp.async,
// BK=64, occupancy 2, per-tile grid (no persistence, no intra-loop prefetch).
// ---------------------------------------------------------------------------
#define BK 64
#define ROW_H 72                                // halves per smem row (64 + 8)
#define MAT_BYTES ((uint32_t)(128 * ROW_H * 2)) // 18432
#define B_OFF     MAT_BYTES
#define STAGE_BYTES (2 * MAT_BYTES)             // 36864
#define NSTAGE 3
#define GEMM_SMEM (NSTAGE * STAGE_BYTES)        // 110592

__global__ __launch_bounds__(256, 2)
void hmma_gemm_f16_kernel(const __half* __restrict__ a,
                          const __half* __restrict__ b,
                          __half* __restrict__ C,
                          int M, int Nreal, int Kpad) {
    extern __shared__ __half smem[];
    const uint32_t smem_u32 = smem_to_u32(smem);
    const int t = threadIdx.x;
    const int lane = t & 31;
    const int wid = t >> 5;
    const int wm = wid & 3;
    const int wn = wid >> 2;
    const int m0 = blockIdx.y * 128;
    const int n0 = blockIdx.x * 128;
    const int nchunk = Kpad / BK;

    float acc[2][8][4];
#pragma unroll
    for (int i = 0; i < 2; ++i)
#pragma unroll
        for (int j = 0; j < 8; ++j)
#pragma unroll
            for (int k = 0; k < 4; ++k) acc[i][j][k] = 0.f;

    auto load_stage = [&](int c) {
        const int slot = c % NSTAGE;
        const int k0 = c * BK;
        const uint32_t sbase = smem_u32 + slot * STAGE_BYTES;
#pragma unroll
        for (int i = 0; i < 4; ++i) {
            int idx = t + i * 256;
            int row = idx >> 3;
            int ch = idx & 7;
            uint32_t off = (uint32_t)(row * ROW_H + ch * 8) * 2;
            int gm = m0 + row;
            bool ok = gm < M;
            int gmc = ok ? gm : 0;
            size_t goa = (size_t)gmc * Kpad + k0 + ch * 8;
            cp_async16(sbase + off, a + goa, ok);
            size_t gob = (size_t)(n0 + row) * Kpad + k0 + ch * 8;
            cp_async16(sbase + off + B_OFF, b + gob, true);
        }
        CP_COMMIT();
    };

    load_stage(0);
    if (nchunk > 1) load_stage(1);

    for (int c = 0; c < nchunk; ++c) {
        if (c + 1 < nchunk) { CP_WAIT(1); } else { CP_WAIT(0); }
        __syncthreads();
        if (c + 2 < nchunk) load_stage(c + 2);

        const uint32_t sb = smem_u32 + (uint32_t)(c % NSTAGE) * STAGE_BYTES;
#pragma unroll
        for (int ks = 0; ks < 4; ++ks) {
            const int k0s = ks * 16;
            uint32_t af[2][4];
            {
                int ar = lane & 15;
                int ak = k0s + (lane >> 4) * 8;
#pragma unroll
                for (int mt = 0; mt < 2; ++mt) {
                    uint32_t addr = sb +
                        (uint32_t)((wm * 32 + mt * 16 + ar) * ROW_H + ak) * 2;
                    ldm_x4(af[mt][0], af[mt][1], af[mt][2], af[mt][3], addr);
                }
            }
            uint32_t bf[8][2];
            {
                int brr = (lane & 7) + (lane >> 4) * 8;
                int bk = k0s + ((lane >> 3) & 1) * 8;
#pragma unroll
                for (int ng = 0; ng < 4; ++ng) {
                    uint32_t addr = sb + B_OFF +
                        (uint32_t)((wn * 64 + ng * 16 + brr) * ROW_H + bk) * 2;
                    uint32_t r0, r1, r2, r3;
                    ldm_x4(r0, r1, r2, r3, addr);
                    bf[2 * ng][0] = r0; bf[2 * ng][1] = r1;
                    bf[2 * ng + 1][0] = r2; bf[2 * ng + 1][1] = r3;
                }
            }
#pragma unroll
            for (int mt = 0; mt < 2; ++mt) {
#pragma unroll
                for (int nt = 0; nt < 8; ++nt) {
                    mma_f16(acc[mt][nt], af[mt], bf[nt]);
                }
            }
        }
    }

    // epilogue: fp16 packed stores
#pragma unroll
    for (int mt = 0; mt < 2; ++mt) {
        int gr0 = m0 + wm * 32 + mt * 16 + (lane >> 2);
#pragma unroll
        for (int nt = 0; nt < 8; ++nt) {
            int gc = n0 + wn * 64 + nt * 8 + (lane & 3) * 2;
            if (gc >= Nreal) continue;
            if (gr0 < M) {
                *reinterpret_cast<uint32_t*>(&C[(size_t)gr0 * Nreal + gc]) =
                    pack_f16x2(acc[mt][nt][0], acc[mt][nt][1]);
            }
            if (gr0 + 8 < M) {
                *reinterpret_cast<uint32_t*>(&C[(size_t)(gr0 + 8) * Nreal + gc]) =
                    pack_f16x2(acc[mt][nt][2], acc[mt][nt][3]);
            }
        }
    }
}

// ---------------------------------------------------------------------------
// Aggregation 1: x1[i,:] = relu(b1 + sum_j t1[j,:]) -> fp16, padded to K2PAD
// ---------------------------------------------------------------------------
__global__ __launch_bounds__(128)
void agg1_kernel(const __half* __restrict__ t,
                 const float* __restrict__ bias,
                 __half* __restrict__ x1) {
    __shared__ int nbr[512];
    const int node = blockIdx.x;
    const int beg = g_offs[node], end = g_offs[node + 1];
    const int deg = end - beg;
    const int* elist;
    if (deg <= 512) {
        for (int i = threadIdx.x; i < deg; i += blockDim.x) nbr[i] = g_eidx[beg + i];
        __syncthreads();
        elist = nbr;
    } else {
        elist = g_eidx + beg;
    }
    const int c = threadIdx.x << 3;
    if (c < D_H1) {
        float a[8];
#pragma unroll
        for (int j = 0; j < 8; ++j) a[j] = bias[c + j];
        for (int e = 0; e < deg; ++e) {
            const uint4 v = *reinterpret_cast<const uint4*>(
                t + (size_t)elist[e] * D_H1 + c);
            const __half2* h = reinterpret_cast<const __half2*>(&v);
#pragma unroll
            for (int j = 0; j < 4; ++j) {
                float2 p = __half22float2(h[j]);
                a[2 * j] += p.x;
                a[2 * j + 1] += p.y;
            }
        }
        uint4 o;
        uint32_t* ow = reinterpret_cast<uint32_t*>(&o);
#pragma unroll
        for (int j = 0; j < 4; ++j)
            ow[j] = pack_f16x2(fmaxf(a[2 * j], 0.f), fmaxf(a[2 * j + 1], 0.f));
        *reinterpret_cast<uint4*>(x1 + (size_t)node * K2PAD + c) = o;
    } else {
        *reinterpret_cast<uint4*>(x1 + (size_t)node * K2PAD + c) =
            make_uint4(0u, 0u, 0u, 0u);
    }
}

// ---------------------------------------------------------------------------
// Fused aggregation 2 + output layer:
//   x2 = relu(b2 + sum_j t2[j,:])  (registers only)
//   out[node,:] = relu(x2 @ W3 + b3)
// 128 threads/node; thread d owns x2 cols [4d, 4d+4); block-reduce 7 outputs.
// ---------------------------------------------------------------------------
__global__ __launch_bounds__(128)
void agg2_out_kernel(const __half* __restrict__ t,
                     const float* __restrict__ bias,
                     const float* __restrict__ W3,
                     const float* __restrict__ b3,
                     float* __restrict__ out) {
    __shared__ int nbr[512];
    __shared__ float Ws[D_H2 * D_OUT];          // 14 KB
    __shared__ float red[4][D_OUT];             // per-warp partials
    const int node = blockIdx.x;
    const int tid = threadIdx.x;
    const int lane = tid & 31;
    const int warp = tid >> 5;

    // load W3 into smem (all threads)
    for (int i = tid; i < D_H2 * D_OUT; i += 128) Ws[i] = W3[i];

    const int beg = g_offs[node], end = g_offs[node + 1];
    const int deg = end - beg;
    const int* elist;
    if (deg <= 512) {
        for (int i = tid; i < deg; i += 128) nbr[i] = g_eidx[beg + i];
        __syncthreads();
        elist = nbr;
    } else {
        __syncthreads();   // Ws visible
        elist = g_eidx + beg;
    }

    const int c = tid << 2;
    float p[D_OUT] = {0.f, 0.f, 0.f, 0.f, 0.f, 0.f, 0.f};
    if (c < D_H2) {        // threads 0..124
        float a0 = bias[c], a1 = bias[c + 1], a2 = bias[c + 2], a3 = bias[c + 3];
        for (int e = 0; e < deg; ++e) {
            const half4 v = *reinterpret_cast<const half4*>(
                t + (size_t)elist[e] * D_H2 + c);
            float2 q0 = __half22float2(v.a);
            float2 q1 = __half22float2(v.b);
            a0 += q0.x; a1 += q0.y; a2 += q1.x; a3 += q1.y;
        }
        a0 = fmaxf(a0, 0.f); a1 = fmaxf(a1, 0.f);
        a2 = fmaxf(a2, 0.f); a3 = fmaxf(a3, 0.f);
        // partial GEMV: p[j] += x2[c+i] * W3[(c+i)*7 + j]
#pragma unroll
        for (int j = 0; j < D_OUT; ++j) {
            p[j] = a0 * Ws[(c + 0) * D_OUT + j]
                 + a1 * Ws[(c + 1) * D_OUT + j]
                 + a2 * Ws[(c + 2) * D_OUT + j]
                 + a3 * Ws[(c + 3) * D_OUT + j];
        }
    }
    // warp reduce
#pragma unroll
    for (int j = 0; j < D_OUT; ++j) {
#pragma unroll
        for (int off = 16; off > 0; off >>= 1)
            p[j] += __shfl_xor_sync(0xFFFFFFFFu, p[j], off);
    }
    if (lane == 0) {
#pragma unroll
        for (int j = 0; j < D_OUT; ++j) red[warp][j] = p[j];
    }
    __syncthreads();
    if (tid < D_OUT) {
        float s = red[0][tid] + red[1][tid] + red[2][tid] + red[3][tid];
        out[(size_t)node * D_OUT + tid] = fmaxf(s + b3[tid], 0.f);
    }
}

// ---------------------------------------------------------------------------
// Launch — gemm1 stays at host-issue index 3 (the ncu capture slot).
// ---------------------------------------------------------------------------
extern "C" void kernel_launch(void* const* d_in, const int* in_sizes, int n_in,
                              void* d_out, int out_size) {
    const float* features = (const float*)d_in[0];
    const int*   src      = (const int*)  d_in[1];
    const int*   dst      = (const int*)  d_in[2];
    const float* W1       = (const float*)d_in[3];
    const float* b1       = (const float*)d_in[4];
    const float* W2       = (const float*)d_in[5];
    const float* b2       = (const float*)d_in[6];
    const float* W3       = (const float*)d_in[7];
    const float* b3       = (const float*)d_in[8];
    float* out = (float*)d_out;

    __half *fa, *w1t, *x1, *w2t, *t1, *t2;
    cudaGetSymbolAddress((void**)&fa, g_fa);
    cudaGetSymbolAddress((void**)&w1t, g_w1t);
    cudaGetSymbolAddress((void**)&x1, g_x1);
    cudaGetSymbolAddress((void**)&w2t, g_w2t);
    cudaGetSymbolAddress((void**)&t1, g_t1);
    cudaGetSymbolAddress((void**)&t2, g_t2);

    cudaFuncSetAttribute(hmma_gemm_f16_kernel,
                         cudaFuncAttributeMaxDynamicSharedMemorySize, GEMM_SMEM);

    // Launch 0: quantize features (+ zero CSR counters)
    {
        size_t tot4 = (size_t)NNODES * (K1PAD / 4);
        quantize_pad_kernel<<<(unsigned)((tot4 + 255) / 256), 256>>>(
            features, fa, NNODES, D_IN, K1PAD);
    }
    // Launches 1-2: weight transposes
    {
        dim3 tb(32, 8);
        dim3 tg1(K1PAD / 32, N1PAD / 32);
        transpose_f16_tiled_kernel<<<tg1, tb>>>(W1, w1t, D_IN, D_H1, K1PAD, N1PAD);
        dim3 tg2(K2PAD / 32, N2PAD / 32);
        transpose_f16_tiled_kernel<<<tg2, tb>>>(W2, w2t, D_H1, D_H2, K2PAD, N2PAD);
    }

    // Launch 3 (ncu capture slot): GEMM 1
    {
        dim3 grid(N1PAD / 128, (NNODES + 127) / 128);
        hmma_gemm_f16_kernel<<<grid, 256, GEMM_SMEM>>>(fa, w1t, t1,
                                                       NNODES, D_H1, K1PAD);
    }

    // CSR build
    count_kernel<<<(NEDGES + 255) / 256, 256>>>(dst);
    scan_kernel<<<1, 1024>>>();
    fill_kernel<<<(NEDGES + 255) / 256, 256>>>(src, dst);

    // Layer 1 aggregation
    agg1_kernel<<<NNODES, 128>>>(t1, b1, x1);

    // Layer 2: GEMM 2 + fused aggregation/output
    {
        dim3 grid(N2PAD / 128, (NNODES + 127) / 128);
        hmma_gemm_f16_kernel<<<grid, 256, GEMM_SMEM>>>(x1, w2t, t2,
                                                       NNODES, D_H2, K2PAD);
        agg2_out_kernel<<<NNODES, 128>>>(t2, b2, W3, b3, out);
    }
}

// round 11
// speedup vs baseline: 1.5155x; 1.5155x over previous
#include <cuda_runtime.h>
#include <cuda_fp16.h>
#include <cstdint>

// Problem constants
#define NNODES 20000
#define NEDGES 200000
#define D_IN   1433
#define D_H1   1000
#define D_H2   500
#define D_OUT  7

// Padded GEMM dims
#define K1PAD  1472   // >= 1433, mult of 64
#define K2PAD  1024   // >= 1000, mult of 64
#define N1PAD  1024   // >= 1000, mult of 128
#define N2PAD  512    // >= 500,  mult of 128

// ---------------------------------------------------------------------------
// Device scratch
// ---------------------------------------------------------------------------
__device__ __align__(256) __half g_fa[(size_t)NNODES * K1PAD];
__device__ __align__(256) __half g_w1t[(size_t)N1PAD * K1PAD];
__device__ __align__(256) __half g_x1[(size_t)NNODES * K2PAD];
__device__ __align__(256) __half g_w2t[(size_t)N2PAD * K2PAD];
__device__ __align__(256) __half g_t1[(size_t)NNODES * D_H1];
__device__ __align__(256) __half g_t2[(size_t)NNODES * D_H2];
__device__ int g_count[NNODES];
__device__ int g_pos[NNODES];
__device__ int g_offs[NNODES + 1];
__device__ int g_eidx[NEDGES];

// ---------------------------------------------------------------------------
// PTX helpers
// ---------------------------------------------------------------------------
__device__ __forceinline__ uint32_t smem_to_u32(const void* p) {
    uint32_t a;
    asm("{ .reg .u64 t; cvta.to.shared.u64 t, %1; cvt.u32.u64 %0, t; }"
        : "=r"(a) : "l"(p));
    return a;
}

__device__ __forceinline__ void cp_async16(uint32_t sdst, const void* gsrc, bool ok) {
    int sz = ok ? 16 : 0;
    asm volatile("cp.async.cg.shared.global [%0], [%1], 16, %2;\n"
                 :: "r"(sdst), "l"(gsrc), "r"(sz));
}
#define CP_COMMIT() asm volatile("cp.async.commit_group;\n" ::: "memory")
#define CP_WAIT(n)  asm volatile("cp.async.wait_group %0;\n" :: "n"(n) : "memory")

__device__ __forceinline__ void ldm_x4(uint32_t& r0, uint32_t& r1, uint32_t& r2,
                                       uint32_t& r3, uint32_t addr) {
    asm volatile("ldmatrix.sync.aligned.m8n8.x4.shared.b16 {%0,%1,%2,%3}, [%4];"
                 : "=r"(r0), "=r"(r1), "=r"(r2), "=r"(r3) : "r"(addr));
}

__device__ __forceinline__ void mma_f16(float* c, const uint32_t* a, const uint32_t* b) {
    asm volatile(
        "mma.sync.aligned.m16n8k16.row.col.f32.f16.f16.f32 "
        "{%0,%1,%2,%3}, {%4,%5,%6,%7}, {%8,%9}, {%0,%1,%2,%3};"
        : "+f"(c[0]), "+f"(c[1]), "+f"(c[2]), "+f"(c[3])
        : "r"(a[0]), "r"(a[1]), "r"(a[2]), "r"(a[3]), "r"(b[0]), "r"(b[1]));
}

__device__ __forceinline__ uint32_t pack_f16x2(float a, float b) {
    __half2 h = __floats2half2_rn(a, b);
    return *reinterpret_cast<uint32_t*>(&h);
}

struct __align__(8) half4 { __half2 a, b; };

// ---------------------------------------------------------------------------
// CSR build (g_count/g_pos zeroed inside quantize_pad_kernel)
// ---------------------------------------------------------------------------
__global__ void count_kernel(const int* __restrict__ dst) {
    int e = blockIdx.x * blockDim.x + threadIdx.x;
    if (e < NEDGES) atomicAdd(&g_count[dst[e]], 1);
}
__global__ void scan_kernel() {
    __shared__ int part[1024];
    const int tid = threadIdx.x;
    const int CH = (NNODES + 1023) / 1024;
    const int base = tid * CH;
    int s = 0;
    for (int i = 0; i < CH; ++i) {
        int idx = base + i;
        if (idx < NNODES) s += g_count[idx];
    }
    part[tid] = s;
    __syncthreads();
    for (int off = 1; off < 1024; off <<= 1) {
        int v = (tid >= off) ? part[tid - off] : 0;
        __syncthreads();
        part[tid] += v;
        __syncthreads();
    }
    int run = part[tid] - s;
    for (int i = 0; i < CH; ++i) {
        int idx = base + i;
        if (idx < NNODES) { g_offs[idx] = run; run += g_count[idx]; }
    }
    if (tid == 1023) g_offs[NNODES] = part[1023];
}
__global__ void fill_kernel(const int* __restrict__ src, const int* __restrict__ dst) {
    int e = blockIdx.x * blockDim.x + threadIdx.x;
    if (e < NEDGES) {
        int d = dst[e];
        int p = atomicAdd(&g_pos[d], 1);
        g_eidx[g_offs[d] + p] = src[e];
    }
}

// ---------------------------------------------------------------------------
// Conversion: fp32 -> fp16, zero-padded; 4 elems/thread. Also zeroes CSR counters.
// ---------------------------------------------------------------------------
__global__ void quantize_pad_kernel(const float* __restrict__ src,
                                    __half* __restrict__ dstq,
                                    int M, int K, int Kpad) {
    size_t idx4 = (size_t)blockIdx.x * blockDim.x + threadIdx.x;
    if (idx4 < NNODES) { g_count[(int)idx4] = 0; g_pos[(int)idx4] = 0; }
    size_t total4 = (size_t)M * (Kpad >> 2);
    if (idx4 >= total4) return;
    int gpr = Kpad >> 2;
    int r = (int)(idx4 / gpr);
    int c = (int)(idx4 % gpr) << 2;
    float v[4];
#pragma unroll
    for (int j = 0; j < 4; ++j) {
        int cj = c + j;
        v[j] = (cj < K) ? src[(size_t)r * K + cj] : 0.f;
    }
    size_t o = (size_t)r * Kpad + c;
    *reinterpret_cast<uint2*>(dstq + o) =
        make_uint2(pack_f16x2(v[0], v[1]), pack_f16x2(v[2], v[3]));
}

// Tiled transpose: W [K,N] fp32 row-major -> Wt fp16 [Npad][Kpad], zero-padded
__global__ void transpose_f16_tiled_kernel(const float* __restrict__ W,
                                           __half* __restrict__ t,
                                           int K, int N, int Kpad, int Npad) {
    __shared__ float tile[32][33];
    const int k0 = blockIdx.x * 32;
    const int n0 = blockIdx.y * 32;
    const int tx = threadIdx.x;
    const int ty = threadIdx.y;
#pragma unroll
    for (int j = 0; j < 32; j += 8) {
        int k = k0 + ty + j, n = n0 + tx;
        tile[ty + j][tx] = (k < K && n < N) ? W[(size_t)k * N + n] : 0.f;
    }
    __syncthreads();
#pragma unroll
    for (int j = 0; j < 32; j += 8) {
        int n = n0 + ty + j, k = k0 + tx;
        if (n < Npad && k < Kpad)
            t[(size_t)n * Kpad + k] = __float2half(tile[tx][ty + j]);
    }
}

// ---------------------------------------------------------------------------
// HMMA GEMM (R7 configuration — frozen local optimum):
// CTA tile 128x128, 8 warps (4m x 2n), warp tile 32x64, 3-stage cp.async,
// BK=64, occupancy 2, per-tile grid.
// ---------------------------------------------------------------------------
#define BK 64
#define ROW_H 72                                // halves per smem row (64 + 8)
#define MAT_BYTES ((uint32_t)(128 * ROW_H * 2)) // 18432
#define B_OFF     MAT_BYTES
#define STAGE_BYTES (2 * MAT_BYTES)             // 36864
#define NSTAGE 3
#define GEMM_SMEM (NSTAGE * STAGE_BYTES)        // 110592

__global__ __launch_bounds__(256, 2)
void hmma_gemm_f16_kernel(const __half* __restrict__ a,
                          const __half* __restrict__ b,
                          __half* __restrict__ C,
                          int M, int Nreal, int Kpad) {
    extern __shared__ __half smem[];
    const uint32_t smem_u32 = smem_to_u32(smem);
    const int t = threadIdx.x;
    const int lane = t & 31;
    const int wid = t >> 5;
    const int wm = wid & 3;
    const int wn = wid >> 2;
    const int m0 = blockIdx.y * 128;
    const int n0 = blockIdx.x * 128;
    const int nchunk = Kpad / BK;

    float acc[2][8][4];
#pragma unroll
    for (int i = 0; i < 2; ++i)
#pragma unroll
        for (int j = 0; j < 8; ++j)
#pragma unroll
            for (int k = 0; k < 4; ++k) acc[i][j][k] = 0.f;

    auto load_stage = [&](int c) {
        const int slot = c % NSTAGE;
        const int k0 = c * BK;
        const uint32_t sbase = smem_u32 + slot * STAGE_BYTES;
#pragma unroll
        for (int i = 0; i < 4; ++i) {
            int idx = t + i * 256;
            int row = idx >> 3;
            int ch = idx & 7;
            uint32_t off = (uint32_t)(row * ROW_H + ch * 8) * 2;
            int gm = m0 + row;
            bool ok = gm < M;
            int gmc = ok ? gm : 0;
            size_t goa = (size_t)gmc * Kpad + k0 + ch * 8;
            cp_async16(sbase + off, a + goa, ok);
            size_t gob = (size_t)(n0 + row) * Kpad + k0 + ch * 8;
            cp_async16(sbase + off + B_OFF, b + gob, true);
        }
        CP_COMMIT();
    };

    load_stage(0);
    if (nchunk > 1) load_stage(1);

    for (int c = 0; c < nchunk; ++c) {
        if (c + 1 < nchunk) { CP_WAIT(1); } else { CP_WAIT(0); }
        __syncthreads();
        if (c + 2 < nchunk) load_stage(c + 2);

        const uint32_t sb = smem_u32 + (uint32_t)(c % NSTAGE) * STAGE_BYTES;
#pragma unroll
        for (int ks = 0; ks < 4; ++ks) {
            const int k0s = ks * 16;
            uint32_t af[2][4];
            {
                int ar = lane & 15;
                int ak = k0s + (lane >> 4) * 8;
#pragma unroll
                for (int mt = 0; mt < 2; ++mt) {
                    uint32_t addr = sb +
                        (uint32_t)((wm * 32 + mt * 16 + ar) * ROW_H + ak) * 2;
                    ldm_x4(af[mt][0], af[mt][1], af[mt][2], af[mt][3], addr);
                }
            }
            uint32_t bf[8][2];
            {
                int brr = (lane & 7) + (lane >> 4) * 8;
                int bk = k0s + ((lane >> 3) & 1) * 8;
#pragma unroll
                for (int ng = 0; ng < 4; ++ng) {
                    uint32_t addr = sb + B_OFF +
                        (uint32_t)((wn * 64 + ng * 16 + brr) * ROW_H + bk) * 2;
                    uint32_t r0, r1, r2, r3;
                    ldm_x4(r0, r1, r2, r3, addr);
                    bf[2 * ng][0] = r0; bf[2 * ng][1] = r1;
                    bf[2 * ng + 1][0] = r2; bf[2 * ng + 1][1] = r3;
                }
            }
#pragma unroll
            for (int mt = 0; mt < 2; ++mt) {
#pragma unroll
                for (int nt = 0; nt < 8; ++nt) {
                    mma_f16(acc[mt][nt], af[mt], bf[nt]);
                }
            }
        }
    }

    // epilogue: fp16 packed stores
#pragma unroll
    for (int mt = 0; mt < 2; ++mt) {
        int gr0 = m0 + wm * 32 + mt * 16 + (lane >> 2);
#pragma unroll
        for (int nt = 0; nt < 8; ++nt) {
            int gc = n0 + wn * 64 + nt * 8 + (lane & 3) * 2;
            if (gc >= Nreal) continue;
            if (gr0 < M) {
                *reinterpret_cast<uint32_t*>(&C[(size_t)gr0 * Nreal + gc]) =
                    pack_f16x2(acc[mt][nt][0], acc[mt][nt][1]);
            }
            if (gr0 + 8 < M) {
                *reinterpret_cast<uint32_t*>(&C[(size_t)(gr0 + 8) * Nreal + gc]) =
                    pack_f16x2(acc[mt][nt][2], acc[mt][nt][3]);
            }
        }
    }
}

// ---------------------------------------------------------------------------
// Aggregation 1: x1[i,:] = relu(b1 + sum_j t1[j,:]) -> fp16, padded to K2PAD
// ---------------------------------------------------------------------------
__global__ __launch_bounds__(128)
void agg1_kernel(const __half* __restrict__ t,
                 const float* __restrict__ bias,
                 __half* __restrict__ x1) {
    __shared__ int nbr[512];
    const int node = blockIdx.x;
    const int beg = g_offs[node], end = g_offs[node + 1];
    const int deg = end - beg;
    const int* elist;
    if (deg <= 512) {
        for (int i = threadIdx.x; i < deg; i += blockDim.x) nbr[i] = g_eidx[beg + i];
        __syncthreads();
        elist = nbr;
    } else {
        elist = g_eidx + beg;
    }
    const int c = threadIdx.x << 3;
    if (c < D_H1) {
        float a[8];
#pragma unroll
        for (int j = 0; j < 8; ++j) a[j] = bias[c + j];
        for (int e = 0; e < deg; ++e) {
            const uint4 v = *reinterpret_cast<const uint4*>(
                t + (size_t)elist[e] * D_H1 + c);
            const __half2* h = reinterpret_cast<const __half2*>(&v);
#pragma unroll
            for (int j = 0; j < 4; ++j) {
                float2 p = __half22float2(h[j]);
                a[2 * j] += p.x;
                a[2 * j + 1] += p.y;
            }
        }
        uint4 o;
        uint32_t* ow = reinterpret_cast<uint32_t*>(&o);
#pragma unroll
        for (int j = 0; j < 4; ++j)
            ow[j] = pack_f16x2(fmaxf(a[2 * j], 0.f), fmaxf(a[2 * j + 1], 0.f));
        *reinterpret_cast<uint4*>(x1 + (size_t)node * K2PAD + c) = o;
    } else {
        *reinterpret_cast<uint4*>(x1 + (size_t)node * K2PAD + c) =
            make_uint4(0u, 0u, 0u, 0u);
    }
}

// ---------------------------------------------------------------------------
// Fused aggregation 2 + output layer, multi-node CTAs:
// each CTA loads W3 once and processes NODES_PER_CTA nodes.
//   x2 = relu(b2 + sum_j t2[j,:])  (registers only)
//   out[node,:] = relu(x2 @ W3 + b3)
// ---------------------------------------------------------------------------
#define NODES_PER_CTA 8

__global__ __launch_bounds__(128)
void agg2_out_kernel(const __half* __restrict__ t,
                     const float* __restrict__ bias,
                     const float* __restrict__ W3,
                     const float* __restrict__ b3,
                     float* __restrict__ out) {
    __shared__ int nbr[512];
    __shared__ float Ws[D_H2 * D_OUT];          // 14 KB
    __shared__ float red[4][D_OUT];
    const int tid = threadIdx.x;
    const int lane = tid & 31;
    const int warp = tid >> 5;
    const int c = tid << 2;

    // load W3 + bias columns once per CTA
    for (int i = tid; i < D_H2 * D_OUT; i += 128) Ws[i] = W3[i];
    float b0 = 0.f, b1v = 0.f, b2v = 0.f, b3v = 0.f;
    if (c < D_H2) {
        b0 = bias[c]; b1v = bias[c + 1]; b2v = bias[c + 2]; b3v = bias[c + 3];
    }

    const int node0 = blockIdx.x * NODES_PER_CTA;
#pragma unroll 1
    for (int ni = 0; ni < NODES_PER_CTA; ++ni) {
        const int node = node0 + ni;
        if (node >= NNODES) break;
        const int beg = g_offs[node], end = g_offs[node + 1];
        const int deg = end - beg;
        __syncthreads();   // nbr/red reuse safety from previous node
        const int* elist;
        if (deg <= 512) {
            for (int i = tid; i < deg; i += 128) nbr[i] = g_eidx[beg + i];
            __syncthreads();
            elist = nbr;
        } else {
            __syncthreads();
            elist = g_eidx + beg;
        }

        float p[D_OUT] = {0.f, 0.f, 0.f, 0.f, 0.f, 0.f, 0.f};
        if (c < D_H2) {
            float a0 = b0, a1 = b1v, a2 = b2v, a3 = b3v;
            for (int e = 0; e < deg; ++e) {
                const half4 v = *reinterpret_cast<const half4*>(
                    t + (size_t)elist[e] * D_H2 + c);
                float2 q0 = __half22float2(v.a);
                float2 q1 = __half22float2(v.b);
                a0 += q0.x; a1 += q0.y; a2 += q1.x; a3 += q1.y;
            }
            a0 = fmaxf(a0, 0.f); a1 = fmaxf(a1, 0.f);
            a2 = fmaxf(a2, 0.f); a3 = fmaxf(a3, 0.f);
#pragma unroll
            for (int j = 0; j < D_OUT; ++j) {
                p[j] = a0 * Ws[(c + 0) * D_OUT + j]
                     + a1 * Ws[(c + 1) * D_OUT + j]
                     + a2 * Ws[(c + 2) * D_OUT + j]
                     + a3 * Ws[(c + 3) * D_OUT + j];
            }
        }
#pragma unroll
        for (int j = 0; j < D_OUT; ++j) {
#pragma unroll
            for (int off = 16; off > 0; off >>= 1)
                p[j] += __shfl_xor_sync(0xFFFFFFFFu, p[j], off);
        }
        if (lane == 0) {
#pragma unroll
            for (int j = 0; j < D_OUT; ++j) red[warp][j] = p[j];
        }
        __syncthreads();
        if (tid < D_OUT) {
            float s = red[0][tid] + red[1][tid] + red[2][tid] + red[3][tid];
            out[(size_t)node * D_OUT + tid] = fmaxf(s + b3[tid], 0.f);
        }
    }
}

// ---------------------------------------------------------------------------
// Launch — gemm1 stays at host-issue index 3 (the ncu capture slot).
// ---------------------------------------------------------------------------
extern "C" void kernel_launch(void* const* d_in, const int* in_sizes, int n_in,
                              void* d_out, int out_size) {
    const float* features = (const float*)d_in[0];
    const int*   src      = (const int*)  d_in[1];
    const int*   dst      = (const int*)  d_in[2];
    const float* W1       = (const float*)d_in[3];
    const float* b1       = (const float*)d_in[4];
    const float* W2       = (const float*)d_in[5];
    const float* b2       = (const float*)d_in[6];
    const float* W3       = (const float*)d_in[7];
    const float* b3       = (const float*)d_in[8];
    float* out = (float*)d_out;

    __half *fa, *w1t, *x1, *w2t, *t1, *t2;
    cudaGetSymbolAddress((void**)&fa, g_fa);
    cudaGetSymbolAddress((void**)&w1t, g_w1t);
    cudaGetSymbolAddress((void**)&x1, g_x1);
    cudaGetSymbolAddress((void**)&w2t, g_w2t);
    cudaGetSymbolAddress((void**)&t1, g_t1);
    cudaGetSymbolAddress((void**)&t2, g_t2);

    cudaFuncSetAttribute(hmma_gemm_f16_kernel,
                         cudaFuncAttributeMaxDynamicSharedMemorySize, GEMM_SMEM);

    // Launch 0: quantize features (+ zero CSR counters)
    {
        size_t tot4 = (size_t)NNODES * (K1PAD / 4);
        quantize_pad_kernel<<<(unsigned)((tot4 + 255) / 256), 256>>>(
            features, fa, NNODES, D_IN, K1PAD);
    }
    // Launches 1-2: weight transposes
    {
        dim3 tb(32, 8);
        dim3 tg1(K1PAD / 32, N1PAD / 32);
        transpose_f16_tiled_kernel<<<tg1, tb>>>(W1, w1t, D_IN, D_H1, K1PAD, N1PAD);
        dim3 tg2(K2PAD / 32, N2PAD / 32);
        transpose_f16_tiled_kernel<<<tg2, tb>>>(W2, w2t, D_H1, D_H2, K2PAD, N2PAD);
    }

    // Launch 3 (ncu capture slot): GEMM 1
    {
        dim3 grid(N1PAD / 128, (NNODES + 127) / 128);
        hmma_gemm_f16_kernel<<<grid, 256, GEMM_SMEM>>>(fa, w1t, t1,
                                                       NNODES, D_H1, K1PAD);
    }

    // CSR build
    count_kernel<<<(NEDGES + 255) / 256, 256>>>(dst);
    scan_kernel<<<1, 1024>>>();
    fill_kernel<<<(NEDGES + 255) / 256, 256>>>(src, dst);

    // Layer 1 aggregation
    agg1_kernel<<<NNODES, 128>>>(t1, b1, x1);

    // Layer 2: GEMM 2 + fused aggregation/output (multi-node CTAs)
    {
        dim3 grid(N2PAD / 128, (NNODES + 127) / 128);
        hmma_gemm_f16_kernel<<<grid, 256, GEMM_SMEM>>>(x1, w2t, t2,
                                                       NNODES, D_H2, K2PAD);
        int blocks = (NNODES + NODES_PER_CTA - 1) / NODES_PER_CTA;
        agg2_out_kernel<<<blocks, 128>>>(t2, b2, W3, b3, out);
    }
}

// round 12
// speedup vs baseline: 1.5549x; 1.0260x over previous
#include <cuda_runtime.h>
#include <cuda_fp16.h>
#include <cstdint>

// Problem constants
#define NNODES 20000
#define NEDGES 200000
#define D_IN   1433
#define D_H1   1000
#define D_H2   500
#define D_OUT  7

// Padded GEMM dims
#define K1PAD  1472   // >= 1433, mult of 64
#define K2PAD  1024   // >= 1000, mult of 64
#define N1PAD  1024   // >= 1000, mult of 128
#define N2PAD  512    // >= 500,  mult of 128

// ---------------------------------------------------------------------------
// Device scratch
// ---------------------------------------------------------------------------
__device__ __align__(256) __half g_fa[(size_t)NNODES * K1PAD];
__device__ __align__(256) __half g_w1t[(size_t)N1PAD * K1PAD];
__device__ __align__(256) __half g_x1[(size_t)NNODES * K2PAD];
__device__ __align__(256) __half g_w2t[(size_t)N2PAD * K2PAD];
__device__ __align__(256) __half g_t1[(size_t)NNODES * D_H1];
__device__ __align__(256) __half g_t2[(size_t)NNODES * D_H2];
__device__ int g_count[NNODES];
__device__ int g_pos[NNODES];
__device__ int g_offs[NNODES + 1];
__device__ int g_eidx[NEDGES];

// ---------------------------------------------------------------------------
// PTX helpers
// ---------------------------------------------------------------------------
__device__ __forceinline__ uint32_t smem_to_u32(const void* p) {
    uint32_t a;
    asm("{ .reg .u64 t; cvta.to.shared.u64 t, %1; cvt.u32.u64 %0, t; }"
        : "=r"(a) : "l"(p));
    return a;
}

__device__ __forceinline__ void cp_async16(uint32_t sdst, const void* gsrc, bool ok) {
    int sz = ok ? 16 : 0;
    asm volatile("cp.async.cg.shared.global [%0], [%1], 16, %2;\n"
                 :: "r"(sdst), "l"(gsrc), "r"(sz));
}
#define CP_COMMIT() asm volatile("cp.async.commit_group;\n" ::: "memory")
#define CP_WAIT(n)  asm volatile("cp.async.wait_group %0;\n" :: "n"(n) : "memory")

__device__ __forceinline__ void ldm_x4(uint32_t& r0, uint32_t& r1, uint32_t& r2,
                                       uint32_t& r3, uint32_t addr) {
    asm volatile("ldmatrix.sync.aligned.m8n8.x4.shared.b16 {%0,%1,%2,%3}, [%4];"
                 : "=r"(r0), "=r"(r1), "=r"(r2), "=r"(r3) : "r"(addr));
}

__device__ __forceinline__ void mma_f16(float* c, const uint32_t* a, const uint32_t* b) {
    asm volatile(
        "mma.sync.aligned.m16n8k16.row.col.f32.f16.f16.f32 "
        "{%0,%1,%2,%3}, {%4,%5,%6,%7}, {%8,%9}, {%0,%1,%2,%3};"
        : "+f"(c[0]), "+f"(c[1]), "+f"(c[2]), "+f"(c[3])
        : "r"(a[0]), "r"(a[1]), "r"(a[2]), "r"(a[3]), "r"(b[0]), "r"(b[1]));
}

__device__ __forceinline__ uint32_t pack_f16x2(float a, float b) {
    __half2 h = __floats2half2_rn(a, b);
    return *reinterpret_cast<uint32_t*>(&h);
}

struct __align__(8) half4 { __half2 a, b; };

// ---------------------------------------------------------------------------
// CSR build (g_count/g_pos zeroed inside quantize_pad_kernel)
// ---------------------------------------------------------------------------
__global__ void count_kernel(const int* __restrict__ dst) {
    int e = blockIdx.x * blockDim.x + threadIdx.x;
    if (e < NEDGES) atomicAdd(&g_count[dst[e]], 1);
}
__global__ void scan_kernel() {
    __shared__ int part[1024];
    const int tid = threadIdx.x;
    const int CH = (NNODES + 1023) / 1024;
    const int base = tid * CH;
    int s = 0;
    for (int i = 0; i < CH; ++i) {
        int idx = base + i;
        if (idx < NNODES) s += g_count[idx];
    }
    part[tid] = s;
    __syncthreads();
    for (int off = 1; off < 1024; off <<= 1) {
        int v = (tid >= off) ? part[tid - off] : 0;
        __syncthreads();
        part[tid] += v;
        __syncthreads();
    }
    int run = part[tid] - s;
    for (int i = 0; i < CH; ++i) {
        int idx = base + i;
        if (idx < NNODES) { g_offs[idx] = run; run += g_count[idx]; }
    }
    if (tid == 1023) g_offs[NNODES] = part[1023];
}
__global__ void fill_kernel(const int* __restrict__ src, const int* __restrict__ dst) {
    int e = blockIdx.x * blockDim.x + threadIdx.x;
    if (e < NEDGES) {
        int d = dst[e];
        int p = atomicAdd(&g_pos[d], 1);
        g_eidx[g_offs[d] + p] = src[e];
    }
}

// ---------------------------------------------------------------------------
// Conversion: fp32 -> fp16, zero-padded; 4 elems/thread. Also zeroes CSR counters.
// ---------------------------------------------------------------------------
__global__ void quantize_pad_kernel(const float* __restrict__ src,
                                    __half* __restrict__ dstq,
                                    int M, int K, int Kpad) {
    size_t idx4 = (size_t)blockIdx.x * blockDim.x + threadIdx.x;
    if (idx4 < NNODES) { g_count[(int)idx4] = 0; g_pos[(int)idx4] = 0; }
    size_t total4 = (size_t)M * (Kpad >> 2);
    if (idx4 >= total4) return;
    int gpr = Kpad >> 2;
    int r = (int)(idx4 / gpr);
    int c = (int)(idx4 % gpr) << 2;
    float v[4];
#pragma unroll
    for (int j = 0; j < 4; ++j) {
        int cj = c + j;
        v[j] = (cj < K) ? src[(size_t)r * K + cj] : 0.f;
    }
    size_t o = (size_t)r * Kpad + c;
    *reinterpret_cast<uint2*>(dstq + o) =
        make_uint2(pack_f16x2(v[0], v[1]), pack_f16x2(v[2], v[3]));
}

// Tiled transpose: W [K,N] fp32 row-major -> Wt fp16 [Npad][Kpad], zero-padded
__global__ void transpose_f16_tiled_kernel(const float* __restrict__ W,
                                           __half* __restrict__ t,
                                           int K, int N, int Kpad, int Npad) {
    __shared__ float tile[32][33];
    const int k0 = blockIdx.x * 32;
    const int n0 = blockIdx.y * 32;
    const int tx = threadIdx.x;
    const int ty = threadIdx.y;
#pragma unroll
    for (int j = 0; j < 32; j += 8) {
        int k = k0 + ty + j, n = n0 + tx;
        tile[ty + j][tx] = (k < K && n < N) ? W[(size_t)k * N + n] : 0.f;
    }
    __syncthreads();
#pragma unroll
    for (int j = 0; j < 32; j += 8) {
        int n = n0 + ty + j, k = k0 + tx;
        if (n < Npad && k < Kpad)
            t[(size_t)n * Kpad + k] = __float2half(tile[tx][ty + j]);
    }
}

// ---------------------------------------------------------------------------
// HMMA GEMM (R7 configuration — frozen local optimum):
// CTA tile 128x128, 8 warps (4m x 2n), warp tile 32x64, 3-stage cp.async,
// BK=64, occupancy 2, per-tile grid.
// ---------------------------------------------------------------------------
#define BK 64
#define ROW_H 72                                // halves per smem row (64 + 8)
#define MAT_BYTES ((uint32_t)(128 * ROW_H * 2)) // 18432
#define B_OFF     MAT_BYTES
#define STAGE_BYTES (2 * MAT_BYTES)             // 36864
#define NSTAGE 3
#define GEMM_SMEM (NSTAGE * STAGE_BYTES)        // 110592

__global__ __launch_bounds__(256, 2)
void hmma_gemm_f16_kernel(const __half* __restrict__ a,
                          const __half* __restrict__ b,
                          __half* __restrict__ C,
                          int M, int Nreal, int Kpad) {
    extern __shared__ __half smem[];
    const uint32_t smem_u32 = smem_to_u32(smem);
    const int t = threadIdx.x;
    const int lane = t & 31;
    const int wid = t >> 5;
    const int wm = wid & 3;
    const int wn = wid >> 2;
    const int m0 = blockIdx.y * 128;
    const int n0 = blockIdx.x * 128;
    const int nchunk = Kpad / BK;

    float acc[2][8][4];
#pragma unroll
    for (int i = 0; i < 2; ++i)
#pragma unroll
        for (int j = 0; j < 8; ++j)
#pragma unroll
            for (int k = 0; k < 4; ++k) acc[i][j][k] = 0.f;

    auto load_stage = [&](int c) {
        const int slot = c % NSTAGE;
        const int k0 = c * BK;
        const uint32_t sbase = smem_u32 + slot * STAGE_BYTES;
#pragma unroll
        for (int i = 0; i < 4; ++i) {
            int idx = t + i * 256;
            int row = idx >> 3;
            int ch = idx & 7;
            uint32_t off = (uint32_t)(row * ROW_H + ch * 8) * 2;
            int gm = m0 + row;
            bool ok = gm < M;
            int gmc = ok ? gm : 0;
            size_t goa = (size_t)gmc * Kpad + k0 + ch * 8;
            cp_async16(sbase + off, a + goa, ok);
            size_t gob = (size_t)(n0 + row) * Kpad + k0 + ch * 8;
            cp_async16(sbase + off + B_OFF, b + gob, true);
        }
        CP_COMMIT();
    };

    load_stage(0);
    if (nchunk > 1) load_stage(1);

    for (int c = 0; c < nchunk; ++c) {
        if (c + 1 < nchunk) { CP_WAIT(1); } else { CP_WAIT(0); }
        __syncthreads();
        if (c + 2 < nchunk) load_stage(c + 2);

        const uint32_t sb = smem_u32 + (uint32_t)(c % NSTAGE) * STAGE_BYTES;
#pragma unroll
        for (int ks = 0; ks < 4; ++ks) {
            const int k0s = ks * 16;
            uint32_t af[2][4];
            {
                int ar = lane & 15;
                int ak = k0s + (lane >> 4) * 8;
#pragma unroll
                for (int mt = 0; mt < 2; ++mt) {
                    uint32_t addr = sb +
                        (uint32_t)((wm * 32 + mt * 16 + ar) * ROW_H + ak) * 2;
                    ldm_x4(af[mt][0], af[mt][1], af[mt][2], af[mt][3], addr);
                }
            }
            uint32_t bf[8][2];
            {
                int brr = (lane & 7) + (lane >> 4) * 8;
                int bk = k0s + ((lane >> 3) & 1) * 8;
#pragma unroll
                for (int ng = 0; ng < 4; ++ng) {
                    uint32_t addr = sb + B_OFF +
                        (uint32_t)((wn * 64 + ng * 16 + brr) * ROW_H + bk) * 2;
                    uint32_t r0, r1, r2, r3;
                    ldm_x4(r0, r1, r2, r3, addr);
                    bf[2 * ng][0] = r0; bf[2 * ng][1] = r1;
                    bf[2 * ng + 1][0] = r2; bf[2 * ng + 1][1] = r3;
                }
            }
#pragma unroll
            for (int mt = 0; mt < 2; ++mt) {
#pragma unroll
                for (int nt = 0; nt < 8; ++nt) {
                    mma_f16(acc[mt][nt], af[mt], bf[nt]);
                }
            }
        }
    }

    // epilogue: fp16 packed stores
#pragma unroll
    for (int mt = 0; mt < 2; ++mt) {
        int gr0 = m0 + wm * 32 + mt * 16 + (lane >> 2);
#pragma unroll
        for (int nt = 0; nt < 8; ++nt) {
            int gc = n0 + wn * 64 + nt * 8 + (lane & 3) * 2;
            if (gc >= Nreal) continue;
            if (gr0 < M) {
                *reinterpret_cast<uint32_t*>(&C[(size_t)gr0 * Nreal + gc]) =
                    pack_f16x2(acc[mt][nt][0], acc[mt][nt][1]);
            }
            if (gr0 + 8 < M) {
                *reinterpret_cast<uint32_t*>(&C[(size_t)(gr0 + 8) * Nreal + gc]) =
                    pack_f16x2(acc[mt][nt][2], acc[mt][nt][3]);
            }
        }
    }
}

// ---------------------------------------------------------------------------
// Aggregation 1: x1[i,:] = relu(b1 + sum_j t1[j,:]) -> fp16, padded to K2PAD
// 4 nodes/CTA, bias in registers, direct uniform-gather of edge ids,
// no smem, no barriers.
// ---------------------------------------------------------------------------
#define AGG1_NODES 4

__global__ __launch_bounds__(128)
void agg1_kernel(const __half* __restrict__ t,
                 const float* __restrict__ bias,
                 __half* __restrict__ x1) {
    const int tid = threadIdx.x;
    const int c = tid << 3;               // 0..1016
    const bool act = c < D_H1;            // threads 0..124
    float b[8];
    if (act) {
#pragma unroll
        for (int j = 0; j < 8; ++j) b[j] = bias[c + j];
    }
    const int node0 = blockIdx.x * AGG1_NODES;
#pragma unroll 1
    for (int ni = 0; ni < AGG1_NODES; ++ni) {
        const int node = node0 + ni;
        if (node >= NNODES) return;
        const int beg = g_offs[node], end = g_offs[node + 1];
        if (act) {
            float a[8];
#pragma unroll
            for (int j = 0; j < 8; ++j) a[j] = b[j];
            for (int e = beg; e < end; ++e) {
                const int s = g_eidx[e];   // warp-uniform -> L1 broadcast
                const uint4 v = *reinterpret_cast<const uint4*>(
                    t + (size_t)s * D_H1 + c);
                const __half2* h = reinterpret_cast<const __half2*>(&v);
#pragma unroll
                for (int j = 0; j < 4; ++j) {
                    float2 p = __half22float2(h[j]);
                    a[2 * j] += p.x;
                    a[2 * j + 1] += p.y;
                }
            }
            uint4 o;
            uint32_t* ow = reinterpret_cast<uint32_t*>(&o);
#pragma unroll
            for (int j = 0; j < 4; ++j)
                ow[j] = pack_f16x2(fmaxf(a[2 * j], 0.f), fmaxf(a[2 * j + 1], 0.f));
            *reinterpret_cast<uint4*>(x1 + (size_t)node * K2PAD + c) = o;
        } else {
            *reinterpret_cast<uint4*>(x1 + (size_t)node * K2PAD + c) =
                make_uint4(0u, 0u, 0u, 0u);
        }
    }
}

// ---------------------------------------------------------------------------
// Fused aggregation 2 + output layer, multi-node CTAs, direct gather:
//   x2 = relu(b2 + sum_j t2[j,:])  (registers only)
//   out[node,:] = relu(x2 @ W3 + b3)
// ---------------------------------------------------------------------------
#define NODES_PER_CTA 8

__global__ __launch_bounds__(128)
void agg2_out_kernel(const __half* __restrict__ t,
                     const float* __restrict__ bias,
                     const float* __restrict__ W3,
                     const float* __restrict__ b3,
                     float* __restrict__ out) {
    __shared__ float Ws[D_H2 * D_OUT];          // 14 KB
    __shared__ float red[4][D_OUT];
    const int tid = threadIdx.x;
    const int lane = tid & 31;
    const int warp = tid >> 5;
    const int c = tid << 2;

    for (int i = tid; i < D_H2 * D_OUT; i += 128) Ws[i] = W3[i];
    float b0 = 0.f, b1v = 0.f, b2v = 0.f, b3v = 0.f;
    if (c < D_H2) {
        b0 = bias[c]; b1v = bias[c + 1]; b2v = bias[c + 2]; b3v = bias[c + 3];
    }
    __syncthreads();   // Ws visible

    const int node0 = blockIdx.x * NODES_PER_CTA;
#pragma unroll 1
    for (int ni = 0; ni < NODES_PER_CTA; ++ni) {
        const int node = node0 + ni;
        if (node >= NNODES) break;
        const int beg = g_offs[node], end = g_offs[node + 1];

        float p[D_OUT] = {0.f, 0.f, 0.f, 0.f, 0.f, 0.f, 0.f};
        if (c < D_H2) {
            float a0 = b0, a1 = b1v, a2 = b2v, a3 = b3v;
            for (int e = beg; e < end; ++e) {
                const int s = g_eidx[e];   // warp-uniform
                const half4 v = *reinterpret_cast<const half4*>(
                    t + (size_t)s * D_H2 + c);
                float2 q0 = __half22float2(v.a);
                float2 q1 = __half22float2(v.b);
                a0 += q0.x; a1 += q0.y; a2 += q1.x; a3 += q1.y;
            }
            a0 = fmaxf(a0, 0.f); a1 = fmaxf(a1, 0.f);
            a2 = fmaxf(a2, 0.f); a3 = fmaxf(a3, 0.f);
#pragma unroll
            for (int j = 0; j < D_OUT; ++j) {
                p[j] = a0 * Ws[(c + 0) * D_OUT + j]
                     + a1 * Ws[(c + 1) * D_OUT + j]
                     + a2 * Ws[(c + 2) * D_OUT + j]
                     + a3 * Ws[(c + 3) * D_OUT + j];
            }
        }
#pragma unroll
        for (int j = 0; j < D_OUT; ++j) {
#pragma unroll
            for (int off = 16; off > 0; off >>= 1)
                p[j] += __shfl_xor_sync(0xFFFFFFFFu, p[j], off);
        }
        if (lane == 0) {
#pragma unroll
            for (int j = 0; j < D_OUT; ++j) red[warp][j] = p[j];
        }
        __syncthreads();
        if (tid < D_OUT) {
            float s = red[0][tid] + red[1][tid] + red[2][tid] + red[3][tid];
            out[(size_t)node * D_OUT + tid] = fmaxf(s + b3[tid], 0.f);
        }
        __syncthreads();   // red reuse safety
    }
}

// ---------------------------------------------------------------------------
// Launch — gemm1 stays at host-issue index 3 (the ncu capture slot).
// ---------------------------------------------------------------------------
extern "C" void kernel_launch(void* const* d_in, const int* in_sizes, int n_in,
                              void* d_out, int out_size) {
    const float* features = (const float*)d_in[0];
    const int*   src      = (const int*)  d_in[1];
    const int*   dst      = (const int*)  d_in[2];
    const float* W1       = (const float*)d_in[3];
    const float* b1       = (const float*)d_in[4];
    const float* W2       = (const float*)d_in[5];
    const float* b2       = (const float*)d_in[6];
    const float* W3       = (const float*)d_in[7];
    const float* b3       = (const float*)d_in[8];
    float* out = (float*)d_out;

    __half *fa, *w1t, *x1, *w2t, *t1, *t2;
    cudaGetSymbolAddress((void**)&fa, g_fa);
    cudaGetSymbolAddress((void**)&w1t, g_w1t);
    cudaGetSymbolAddress((void**)&x1, g_x1);
    cudaGetSymbolAddress((void**)&w2t, g_w2t);
    cudaGetSymbolAddress((void**)&t1, g_t1);
    cudaGetSymbolAddress((void**)&t2, g_t2);

    cudaFuncSetAttribute(hmma_gemm_f16_kernel,
                         cudaFuncAttributeMaxDynamicSharedMemorySize, GEMM_SMEM);

    // Launch 0: quantize features (+ zero CSR counters)
    {
        size_t tot4 = (size_t)NNODES * (K1PAD / 4);
        quantize_pad_kernel<<<(unsigned)((tot4 + 255) / 256), 256>>>(
            features, fa, NNODES, D_IN, K1PAD);
    }
    // Launches 1-2: weight transposes
    {
        dim3 tb(32, 8);
        dim3 tg1(K1PAD / 32, N1PAD / 32);
        transpose_f16_tiled_kernel<<<tg1, tb>>>(W1, w1t, D_IN, D_H1, K1PAD, N1PAD);
        dim3 tg2(K2PAD / 32, N2PAD / 32);
        transpose_f16_tiled_kernel<<<tg2, tb>>>(W2, w2t, D_H1, D_H2, K2PAD, N2PAD);
    }

    // Launch 3 (ncu capture slot): GEMM 1
    {
        dim3 grid(N1PAD / 128, (NNODES + 127) / 128);
        hmma_gemm_f16_kernel<<<grid, 256, GEMM_SMEM>>>(fa, w1t, t1,
                                                       NNODES, D_H1, K1PAD);
    }

    // CSR build
    count_kernel<<<(NEDGES + 255) / 256, 256>>>(dst);
    scan_kernel<<<1, 1024>>>();
    fill_kernel<<<(NEDGES + 255) / 256, 256>>>(src, dst);

    // Layer 1 aggregation (4 nodes/CTA)
    {
        int blocks = (NNODES + AGG1_NODES - 1) / AGG1_NODES;
        agg1_kernel<<<blocks, 128>>>(t1, b1, x1);
    }

    // Layer 2: GEMM 2 + fused aggregation/output (8 nodes/CTA)
    {
        dim3 grid(N2PAD / 128, (NNODES + 127) / 128);
        hmma_gemm_f16_kernel<<<grid, 256, GEMM_SMEM>>>(x1, w2t, t2,
                                                       NNODES, D_H2, K2PAD);
        int blocks = (NNODES + NODES_PER_CTA - 1) / NODES_PER_CTA;
        agg2_out_kernel<<<blocks, 128>>>(t2, b2, W3, b3, out);
    }
}

// round 13
// speedup vs baseline: 1.5787x; 1.0153x over previous
#include <cuda_runtime.h>
#include <cuda_fp16.h>
#include <cstdint>

// Problem constants
#define NNODES 20000
#define NEDGES 200000
#define D_IN   1433
#define D_H1   1000
#define D_H2   500
#define D_OUT  7

// Padded GEMM dims
#define K1PAD  1472   // >= 1433, mult of 64
#define K2PAD  1024   // >= 1000, mult of 64
#define N1PAD  1024   // >= 1000, mult of 128
#define N2PAD  512    // >= 500,  mult of 128

// ---------------------------------------------------------------------------
// Device scratch
// ---------------------------------------------------------------------------
__device__ __align__(256) __half g_fa[(size_t)NNODES * K1PAD];
__device__ __align__(256) __half g_w1t[(size_t)N1PAD * K1PAD];
__device__ __align__(256) __half g_x1[(size_t)NNODES * K2PAD];
__device__ __align__(256) __half g_w2t[(size_t)N2PAD * K2PAD];
__device__ __align__(256) __half g_t1[(size_t)NNODES * D_H1];
__device__ __align__(256) __half g_t2[(size_t)NNODES * D_H2];
// Invariant: g_count/g_pos are ZERO at kernel_launch entry.
// (zero-initialized at load; re-zeroed by agg2_out at the end of every call)
__device__ int g_count[NNODES];
__device__ int g_pos[NNODES];
__device__ int g_offs[NNODES + 1];
__device__ int g_eidx[NEDGES];

// ---------------------------------------------------------------------------
// PTX helpers
// ---------------------------------------------------------------------------
__device__ __forceinline__ uint32_t smem_to_u32(const void* p) {
    uint32_t a;
    asm("{ .reg .u64 t; cvta.to.shared.u64 t, %1; cvt.u32.u64 %0, t; }"
        : "=r"(a) : "l"(p));
    return a;
}

__device__ __forceinline__ void cp_async16(uint32_t sdst, const void* gsrc, bool ok) {
    int sz = ok ? 16 : 0;
    asm volatile("cp.async.cg.shared.global [%0], [%1], 16, %2;\n"
                 :: "r"(sdst), "l"(gsrc), "r"(sz));
}
#define CP_COMMIT() asm volatile("cp.async.commit_group;\n" ::: "memory")
#define CP_WAIT(n)  asm volatile("cp.async.wait_group %0;\n" :: "n"(n) : "memory")

__device__ __forceinline__ void ldm_x4(uint32_t& r0, uint32_t& r1, uint32_t& r2,
                                       uint32_t& r3, uint32_t addr) {
    asm volatile("ldmatrix.sync.aligned.m8n8.x4.shared.b16 {%0,%1,%2,%3}, [%4];"
                 : "=r"(r0), "=r"(r1), "=r"(r2), "=r"(r3) : "r"(addr));
}

__device__ __forceinline__ void mma_f16(float* c, const uint32_t* a, const uint32_t* b) {
    asm volatile(
        "mma.sync.aligned.m16n8k16.row.col.f32.f16.f16.f32 "
        "{%0,%1,%2,%3}, {%4,%5,%6,%7}, {%8,%9}, {%0,%1,%2,%3};"
        : "+f"(c[0]), "+f"(c[1]), "+f"(c[2]), "+f"(c[3])
        : "r"(a[0]), "r"(a[1]), "r"(a[2]), "r"(a[3]), "r"(b[0]), "r"(b[1]));
}

__device__ __forceinline__ uint32_t pack_f16x2(float a, float b) {
    __half2 h = __floats2half2_rn(a, b);
    return *reinterpret_cast<uint32_t*>(&h);
}

struct __align__(8) half4 { __half2 a, b; };

// ---------------------------------------------------------------------------
// Launch 0: quantize features (fp32 -> fp16, zero-padded) + CSR count
// (independent work fused into one launch; counters are pre-zeroed)
// ---------------------------------------------------------------------------
__global__ void quantize_count_kernel(const float* __restrict__ src,
                                      __half* __restrict__ dstq,
                                      const int* __restrict__ dst,
                                      int M, int K, int Kpad) {
    size_t idx4 = (size_t)blockIdx.x * blockDim.x + threadIdx.x;
    if (idx4 < NEDGES) atomicAdd(&g_count[dst[idx4]], 1);
    size_t total4 = (size_t)M * (Kpad >> 2);
    if (idx4 >= total4) return;
    int gpr = Kpad >> 2;
    int r = (int)(idx4 / gpr);
    int c = (int)(idx4 % gpr) << 2;
    float v[4];
#pragma unroll
    for (int j = 0; j < 4; ++j) {
        int cj = c + j;
        v[j] = (cj < K) ? src[(size_t)r * K + cj] : 0.f;
    }
    size_t o = (size_t)r * Kpad + c;
    *reinterpret_cast<uint2*>(dstq + o) =
        make_uint2(pack_f16x2(v[0], v[1]), pack_f16x2(v[2], v[3]));
}

// ---------------------------------------------------------------------------
// Launch 1: both weight transposes in one launch (z selects the matrix).
// W [K,N] fp32 row-major -> Wt fp16 [Npad][Kpad], zero-padded.
// ---------------------------------------------------------------------------
__global__ void transpose_both_kernel(const float* __restrict__ W1,
                                      __half* __restrict__ t1,
                                      const float* __restrict__ W2,
                                      __half* __restrict__ t2) {
    __shared__ float tile[32][33];
    const float* W;
    __half* t;
    int K, N, Kpad, Npad;
    if (blockIdx.z == 0) {
        W = W1; t = t1; K = D_IN;  N = D_H1; Kpad = K1PAD; Npad = N1PAD;
    } else {
        W = W2; t = t2; K = D_H1;  N = D_H2; Kpad = K2PAD; Npad = N2PAD;
    }
    const int k0 = blockIdx.x * 32;
    const int n0 = blockIdx.y * 32;
    if (k0 >= Kpad || n0 >= Npad) return;
    const int tx = threadIdx.x;
    const int ty = threadIdx.y;
#pragma unroll
    for (int j = 0; j < 32; j += 8) {
        int k = k0 + ty + j, n = n0 + tx;
        tile[ty + j][tx] = (k < K && n < N) ? W[(size_t)k * N + n] : 0.f;
    }
    __syncthreads();
#pragma unroll
    for (int j = 0; j < 32; j += 8) {
        int n = n0 + ty + j, k = k0 + tx;
        if (n < Npad && k < Kpad)
            t[(size_t)n * Kpad + k] = __float2half(tile[tx][ty + j]);
    }
}

// ---------------------------------------------------------------------------
// Launch 2: exclusive scan of g_count -> g_offs (count done in launch 0)
// ---------------------------------------------------------------------------
__global__ void scan_kernel() {
    __shared__ int part[1024];
    const int tid = threadIdx.x;
    const int CH = (NNODES + 1023) / 1024;
    const int base = tid * CH;
    int s = 0;
    for (int i = 0; i < CH; ++i) {
        int idx = base + i;
        if (idx < NNODES) s += g_count[idx];
    }
    part[tid] = s;
    __syncthreads();
    for (int off = 1; off < 1024; off <<= 1) {
        int v = (tid >= off) ? part[tid - off] : 0;
        __syncthreads();
        part[tid] += v;
        __syncthreads();
    }
    int run = part[tid] - s;
    for (int i = 0; i < CH; ++i) {
        int idx = base + i;
        if (idx < NNODES) { g_offs[idx] = run; run += g_count[idx]; }
    }
    if (tid == 1023) g_offs[NNODES] = part[1023];
}

__global__ void fill_kernel(const int* __restrict__ src, const int* __restrict__ dst) {
    int e = blockIdx.x * blockDim.x + threadIdx.x;
    if (e < NEDGES) {
        int d = dst[e];
        int p = atomicAdd(&g_pos[d], 1);
        g_eidx[g_offs[d] + p] = src[e];
    }
}

// ---------------------------------------------------------------------------
// HMMA GEMM (R7 configuration — frozen local optimum):
// CTA tile 128x128, 8 warps (4m x 2n), warp tile 32x64, 3-stage cp.async,
// BK=64, occupancy 2, per-tile grid.
// ---------------------------------------------------------------------------
#define BK 64
#define ROW_H 72                                // halves per smem row (64 + 8)
#define MAT_BYTES ((uint32_t)(128 * ROW_H * 2)) // 18432
#define B_OFF     MAT_BYTES
#define STAGE_BYTES (2 * MAT_BYTES)             // 36864
#define NSTAGE 3
#define GEMM_SMEM (NSTAGE * STAGE_BYTES)        // 110592

__global__ __launch_bounds__(256, 2)
void hmma_gemm_f16_kernel(const __half* __restrict__ a,
                          const __half* __restrict__ b,
                          __half* __restrict__ C,
                          int M, int Nreal, int Kpad) {
    extern __shared__ __half smem[];
    const uint32_t smem_u32 = smem_to_u32(smem);
    const int t = threadIdx.x;
    const int lane = t & 31;
    const int wid = t >> 5;
    const int wm = wid & 3;
    const int wn = wid >> 2;
    const int m0 = blockIdx.y * 128;
    const int n0 = blockIdx.x * 128;
    const int nchunk = Kpad / BK;

    float acc[2][8][4];
#pragma unroll
    for (int i = 0; i < 2; ++i)
#pragma unroll
        for (int j = 0; j < 8; ++j)
#pragma unroll
            for (int k = 0; k < 4; ++k) acc[i][j][k] = 0.f;

    auto load_stage = [&](int c) {
        const int slot = c % NSTAGE;
        const int k0 = c * BK;
        const uint32_t sbase = smem_u32 + slot * STAGE_BYTES;
#pragma unroll
        for (int i = 0; i < 4; ++i) {
            int idx = t + i * 256;
            int row = idx >> 3;
            int ch = idx & 7;
            uint32_t off = (uint32_t)(row * ROW_H + ch * 8) * 2;
            int gm = m0 + row;
            bool ok = gm < M;
            int gmc = ok ? gm : 0;
            size_t goa = (size_t)gmc * Kpad + k0 + ch * 8;
            cp_async16(sbase + off, a + goa, ok);
            size_t gob = (size_t)(n0 + row) * Kpad + k0 + ch * 8;
            cp_async16(sbase + off + B_OFF, b + gob, true);
        }
        CP_COMMIT();
    };

    load_stage(0);
    if (nchunk > 1) load_stage(1);

    for (int c = 0; c < nchunk; ++c) {
        if (c + 1 < nchunk) { CP_WAIT(1); } else { CP_WAIT(0); }
        __syncthreads();
        if (c + 2 < nchunk) load_stage(c + 2);

        const uint32_t sb = smem_u32 + (uint32_t)(c % NSTAGE) * STAGE_BYTES;
#pragma unroll
        for (int ks = 0; ks < 4; ++ks) {
            const int k0s = ks * 16;
            uint32_t af[2][4];
            {
                int ar = lane & 15;
                int ak = k0s + (lane >> 4) * 8;
#pragma unroll
                for (int mt = 0; mt < 2; ++mt) {
                    uint32_t addr = sb +
                        (uint32_t)((wm * 32 + mt * 16 + ar) * ROW_H + ak) * 2;
                    ldm_x4(af[mt][0], af[mt][1], af[mt][2], af[mt][3], addr);
                }
            }
            uint32_t bf[8][2];
            {
                int brr = (lane & 7) + (lane >> 4) * 8;
                int bk = k0s + ((lane >> 3) & 1) * 8;
#pragma unroll
                for (int ng = 0; ng < 4; ++ng) {
                    uint32_t addr = sb + B_OFF +
                        (uint32_t)((wn * 64 + ng * 16 + brr) * ROW_H + bk) * 2;
                    uint32_t r0, r1, r2, r3;
                    ldm_x4(r0, r1, r2, r3, addr);
                    bf[2 * ng][0] = r0; bf[2 * ng][1] = r1;
                    bf[2 * ng + 1][0] = r2; bf[2 * ng + 1][1] = r3;
                }
            }
#pragma unroll
            for (int mt = 0; mt < 2; ++mt) {
#pragma unroll
                for (int nt = 0; nt < 8; ++nt) {
                    mma_f16(acc[mt][nt], af[mt], bf[nt]);
                }
            }
        }
    }

    // epilogue: fp16 packed stores
#pragma unroll
    for (int mt = 0; mt < 2; ++mt) {
        int gr0 = m0 + wm * 32 + mt * 16 + (lane >> 2);
#pragma unroll
        for (int nt = 0; nt < 8; ++nt) {
            int gc = n0 + wn * 64 + nt * 8 + (lane & 3) * 2;
            if (gc >= Nreal) continue;
            if (gr0 < M) {
                *reinterpret_cast<uint32_t*>(&C[(size_t)gr0 * Nreal + gc]) =
                    pack_f16x2(acc[mt][nt][0], acc[mt][nt][1]);
            }
            if (gr0 + 8 < M) {
                *reinterpret_cast<uint32_t*>(&C[(size_t)(gr0 + 8) * Nreal + gc]) =
                    pack_f16x2(acc[mt][nt][2], acc[mt][nt][3]);
            }
        }
    }
}

// ---------------------------------------------------------------------------
// Aggregation 1: x1[i,:] = relu(b1 + sum_j t1[j,:]) -> fp16, padded to K2PAD
// 4 nodes/CTA, bias in registers, direct uniform-gather, no smem/barriers.
// ---------------------------------------------------------------------------
#define AGG1_NODES 4

__global__ __launch_bounds__(128)
void agg1_kernel(const __half* __restrict__ t,
                 const float* __restrict__ bias,
                 __half* __restrict__ x1) {
    const int tid = threadIdx.x;
    const int c = tid << 3;               // 0..1016
    const bool act = c < D_H1;            // threads 0..124
    float b[8];
    if (act) {
#pragma unroll
        for (int j = 0; j < 8; ++j) b[j] = bias[c + j];
    }
    const int node0 = blockIdx.x * AGG1_NODES;
#pragma unroll 1
    for (int ni = 0; ni < AGG1_NODES; ++ni) {
        const int node = node0 + ni;
        if (node >= NNODES) return;
        const int beg = g_offs[node], end = g_offs[node + 1];
        if (act) {
            float a[8];
#pragma unroll
            for (int j = 0; j < 8; ++j) a[j] = b[j];
            for (int e = beg; e < end; ++e) {
                const int s = g_eidx[e];   // warp-uniform -> L1 broadcast
                const uint4 v = *reinterpret_cast<const uint4*>(
                    t + (size_t)s * D_H1 + c);
                const __half2* h = reinterpret_cast<const __half2*>(&v);
#pragma unroll
                for (int j = 0; j < 4; ++j) {
                    float2 p = __half22float2(h[j]);
                    a[2 * j] += p.x;
                    a[2 * j + 1] += p.y;
                }
            }
            uint4 o;
            uint32_t* ow = reinterpret_cast<uint32_t*>(&o);
#pragma unroll
            for (int j = 0; j < 4; ++j)
                ow[j] = pack_f16x2(fmaxf(a[2 * j], 0.f), fmaxf(a[2 * j + 1], 0.f));
            *reinterpret_cast<uint4*>(x1 + (size_t)node * K2PAD + c) = o;
        } else {
            *reinterpret_cast<uint4*>(x1 + (size_t)node * K2PAD + c) =
                make_uint4(0u, 0u, 0u, 0u);
        }
    }
}

// ---------------------------------------------------------------------------
// Fused aggregation 2 + output layer + counter re-zero (for next call).
//   x2 = relu(b2 + sum_j t2[j,:])  (registers only)
//   out[node,:] = relu(x2 @ W3 + b3)
// ---------------------------------------------------------------------------
#define NODES_PER_CTA 8

__global__ __launch_bounds__(128)
void agg2_out_kernel(const __half* __restrict__ t,
                     const float* __restrict__ bias,
                     const float* __restrict__ W3,
                     const float* __restrict__ b3,
                     float* __restrict__ out) {
    __shared__ float Ws[D_H2 * D_OUT];          // 14 KB
    __shared__ float red[4][D_OUT];
    const int tid = threadIdx.x;
    const int lane = tid & 31;
    const int warp = tid >> 5;
    const int c = tid << 2;

    // re-zero CSR counters for the next invocation (invariant keeper)
    {
        int g = blockIdx.x * 128 + tid;
        if (g < NNODES) { g_count[g] = 0; g_pos[g] = 0; }
    }

    for (int i = tid; i < D_H2 * D_OUT; i += 128) Ws[i] = W3[i];
    float b0 = 0.f, b1v = 0.f, b2v = 0.f, b3v = 0.f;
    if (c < D_H2) {
        b0 = bias[c]; b1v = bias[c + 1]; b2v = bias[c + 2]; b3v = bias[c + 3];
    }
    __syncthreads();   // Ws visible

    const int node0 = blockIdx.x * NODES_PER_CTA;
#pragma unroll 1
    for (int ni = 0; ni < NODES_PER_CTA; ++ni) {
        const int node = node0 + ni;
        if (node >= NNODES) break;
        const int beg = g_offs[node], end = g_offs[node + 1];

        float p[D_OUT] = {0.f, 0.f, 0.f, 0.f, 0.f, 0.f, 0.f};
        if (c < D_H2) {
            float a0 = b0, a1 = b1v, a2 = b2v, a3 = b3v;
            for (int e = beg; e < end; ++e) {
                const int s = g_eidx[e];   // warp-uniform
                const half4 v = *reinterpret_cast<const half4*>(
                    t + (size_t)s * D_H2 + c);
                float2 q0 = __half22float2(v.a);
                float2 q1 = __half22float2(v.b);
                a0 += q0.x; a1 += q0.y; a2 += q1.x; a3 += q1.y;
            }
            a0 = fmaxf(a0, 0.f); a1 = fmaxf(a1, 0.f);
            a2 = fmaxf(a2, 0.f); a3 = fmaxf(a3, 0.f);
#pragma unroll
            for (int j = 0; j < D_OUT; ++j) {
                p[j] = a0 * Ws[(c + 0) * D_OUT + j]
                     + a1 * Ws[(c + 1) * D_OUT + j]
                     + a2 * Ws[(c + 2) * D_OUT + j]
                     + a3 * Ws[(c + 3) * D_OUT + j];
            }
        }
#pragma unroll
        for (int j = 0; j < D_OUT; ++j) {
#pragma unroll
            for (int off = 16; off > 0; off >>= 1)
                p[j] += __shfl_xor_sync(0xFFFFFFFFu, p[j], off);
        }
        if (lane == 0) {
#pragma unroll
            for (int j = 0; j < D_OUT; ++j) red[warp][j] = p[j];
        }
        __syncthreads();
        if (tid < D_OUT) {
            float s = red[0][tid] + red[1][tid] + red[2][tid] + red[3][tid];
            out[(size_t)node * D_OUT + tid] = fmaxf(s + b3[tid], 0.f);
        }
        __syncthreads();   // red reuse safety
    }
}

// ---------------------------------------------------------------------------
// Launch — 8 launches; gemm1 stays at host-issue index 3 (ncu capture slot).
// ---------------------------------------------------------------------------
extern "C" void kernel_launch(void* const* d_in, const int* in_sizes, int n_in,
                              void* d_out, int out_size) {
    const float* features = (const float*)d_in[0];
    const int*   src      = (const int*)  d_in[1];
    const int*   dst      = (const int*)  d_in[2];
    const float* W1       = (const float*)d_in[3];
    const float* b1       = (const float*)d_in[4];
    const float* W2       = (const float*)d_in[5];
    const float* b2       = (const float*)d_in[6];
    const float* W3       = (const float*)d_in[7];
    const float* b3       = (const float*)d_in[8];
    float* out = (float*)d_out;

    __half *fa, *w1t, *x1, *w2t, *t1, *t2;
    cudaGetSymbolAddress((void**)&fa, g_fa);
    cudaGetSymbolAddress((void**)&w1t, g_w1t);
    cudaGetSymbolAddress((void**)&x1, g_x1);
    cudaGetSymbolAddress((void**)&w2t, g_w2t);
    cudaGetSymbolAddress((void**)&t1, g_t1);
    cudaGetSymbolAddress((void**)&t2, g_t2);

    cudaFuncSetAttribute(hmma_gemm_f16_kernel,
                         cudaFuncAttributeMaxDynamicSharedMemorySize, GEMM_SMEM);

    // Launch 0: quantize features + CSR count (counters pre-zeroed)
    {
        size_t tot4 = (size_t)NNODES * (K1PAD / 4);
        quantize_count_kernel<<<(unsigned)((tot4 + 255) / 256), 256>>>(
            features, fa, dst, NNODES, D_IN, K1PAD);
    }
    // Launch 1: both weight transposes
    {
        dim3 tb(32, 8);
        dim3 tg(K1PAD / 32, N1PAD / 32, 2);   // covers W2's smaller extent too
        transpose_both_kernel<<<tg, tb>>>(W1, w1t, W2, w2t);
    }
    // Launch 2: CSR scan (count completed in launch 0)
    scan_kernel<<<1, 1024>>>();

    // Launch 3 (ncu capture slot): GEMM 1
    {
        dim3 grid(N1PAD / 128, (NNODES + 127) / 128);
        hmma_gemm_f16_kernel<<<grid, 256, GEMM_SMEM>>>(fa, w1t, t1,
                                                       NNODES, D_H1, K1PAD);
    }

    // Launch 4: CSR fill
    fill_kernel<<<(NEDGES + 255) / 256, 256>>>(src, dst);

    // Launch 5: layer-1 aggregation (4 nodes/CTA)
    {
        int blocks = (NNODES + AGG1_NODES - 1) / AGG1_NODES;
        agg1_kernel<<<blocks, 128>>>(t1, b1, x1);
    }

    // Launch 6: GEMM 2
    {
        dim3 grid(N2PAD / 128, (NNODES + 127) / 128);
        hmma_gemm_f16_kernel<<<grid, 256, GEMM_SMEM>>>(x1, w2t, t2,
                                                       NNODES, D_H2, K2PAD);
    }
    // Launch 7: fused aggregation 2 + output (+ counter re-zero)
    {
        int blocks = (NNODES + NODES_PER_CTA - 1) / NODES_PER_CTA;
        agg2_out_kernel<<<blocks, 128>>>(t2, b2, W3, b3, out);
    }
}

// round 14
// speedup vs baseline: 1.6196x; 1.0259x over previous
#include <cuda_runtime.h>
#include <cuda_fp16.h>
#include <cstdint>

// Problem constants
#define NNODES 20000
#define NEDGES 200000
#define D_IN   1433
#define D_H1   1000
#define D_H2   500
#define D_OUT  7

// Padded GEMM dims
#define K1PAD  1472   // >= 1433, mult of 64
#define K2PAD  1024   // >= 1000, mult of 64
#define N1PAD  1024   // >= 1000, mult of 128
#define N2PAD  512    // >= 500,  mult of 128

// ---------------------------------------------------------------------------
// Device scratch
// ---------------------------------------------------------------------------
__device__ __align__(256) __half g_fa[(size_t)NNODES * K1PAD];
__device__ __align__(256) __half g_w1t[(size_t)N1PAD * K1PAD];
__device__ __align__(256) __half g_x1[(size_t)NNODES * K2PAD];
__device__ __align__(256) __half g_w2t[(size_t)N2PAD * K2PAD];
__device__ __align__(256) __half g_t1[(size_t)NNODES * D_H1];
__device__ __align__(256) __half g_t2[(size_t)NNODES * D_H2];
// Invariant: g_count/g_pos are ZERO at kernel_launch entry.
// (zero-initialized at load; re-zeroed by agg2_out at the end of every call)
__device__ int g_count[NNODES];
__device__ int g_pos[NNODES];
__device__ int g_offs[NNODES + 1];
__device__ int g_eidx[NEDGES];

// ---------------------------------------------------------------------------
// PTX helpers
// ---------------------------------------------------------------------------
__device__ __forceinline__ uint32_t smem_to_u32(const void* p) {
    uint32_t a;
    asm("{ .reg .u64 t; cvta.to.shared.u64 t, %1; cvt.u32.u64 %0, t; }"
        : "=r"(a) : "l"(p));
    return a;
}

__device__ __forceinline__ void cp_async16(uint32_t sdst, const void* gsrc, bool ok) {
    int sz = ok ? 16 : 0;
    asm volatile("cp.async.cg.shared.global [%0], [%1], 16, %2;\n"
                 :: "r"(sdst), "l"(gsrc), "r"(sz));
}
#define CP_COMMIT() asm volatile("cp.async.commit_group;\n" ::: "memory")
#define CP_WAIT(n)  asm volatile("cp.async.wait_group %0;\n" :: "n"(n) : "memory")

__device__ __forceinline__ void ldm_x4(uint32_t& r0, uint32_t& r1, uint32_t& r2,
                                       uint32_t& r3, uint32_t addr) {
    asm volatile("ldmatrix.sync.aligned.m8n8.x4.shared.b16 {%0,%1,%2,%3}, [%4];"
                 : "=r"(r0), "=r"(r1), "=r"(r2), "=r"(r3) : "r"(addr));
}

__device__ __forceinline__ void mma_f16(float* c, const uint32_t* a, const uint32_t* b) {
    asm volatile(
        "mma.sync.aligned.m16n8k16.row.col.f32.f16.f16.f32 "
        "{%0,%1,%2,%3}, {%4,%5,%6,%7}, {%8,%9}, {%0,%1,%2,%3};"
        : "+f"(c[0]), "+f"(c[1]), "+f"(c[2]), "+f"(c[3])
        : "r"(a[0]), "r"(a[1]), "r"(a[2]), "r"(a[3]), "r"(b[0]), "r"(b[1]));
}

__device__ __forceinline__ uint32_t pack_f16x2(float a, float b) {
    __half2 h = __floats2half2_rn(a, b);
    return *reinterpret_cast<uint32_t*>(&h);
}

struct __align__(8) half4 { __half2 a, b; };

// ---------------------------------------------------------------------------
// quantize features (fp32 -> fp16, zero-padded) + CSR count
// ---------------------------------------------------------------------------
__global__ void quantize_count_kernel(const float* __restrict__ src,
                                      __half* __restrict__ dstq,
                                      const int* __restrict__ dst,
                                      int M, int K, int Kpad) {
    size_t idx4 = (size_t)blockIdx.x * blockDim.x + threadIdx.x;
    if (idx4 < NEDGES) atomicAdd(&g_count[dst[idx4]], 1);
    size_t total4 = (size_t)M * (Kpad >> 2);
    if (idx4 >= total4) return;
    int gpr = Kpad >> 2;
    int r = (int)(idx4 / gpr);
    int c = (int)(idx4 % gpr) << 2;
    float v[4];
#pragma unroll
    for (int j = 0; j < 4; ++j) {
        int cj = c + j;
        v[j] = (cj < K) ? src[(size_t)r * K + cj] : 0.f;
    }
    size_t o = (size_t)r * Kpad + c;
    *reinterpret_cast<uint2*>(dstq + o) =
        make_uint2(pack_f16x2(v[0], v[1]), pack_f16x2(v[2], v[3]));
}

// ---------------------------------------------------------------------------
// both weight transposes in one launch (z selects the matrix)
// ---------------------------------------------------------------------------
__global__ void transpose_both_kernel(const float* __restrict__ W1,
                                      __half* __restrict__ t1,
                                      const float* __restrict__ W2,
                                      __half* __restrict__ t2) {
    __shared__ float tile[32][33];
    const float* W;
    __half* t;
    int K, N, Kpad, Npad;
    if (blockIdx.z == 0) {
        W = W1; t = t1; K = D_IN;  N = D_H1; Kpad = K1PAD; Npad = N1PAD;
    } else {
        W = W2; t = t2; K = D_H1;  N = D_H2; Kpad = K2PAD; Npad = N2PAD;
    }
    const int k0 = blockIdx.x * 32;
    const int n0 = blockIdx.y * 32;
    if (k0 >= Kpad || n0 >= Npad) return;
    const int tx = threadIdx.x;
    const int ty = threadIdx.y;
#pragma unroll
    for (int j = 0; j < 32; j += 8) {
        int k = k0 + ty + j, n = n0 + tx;
        tile[ty + j][tx] = (k < K && n < N) ? W[(size_t)k * N + n] : 0.f;
    }
    __syncthreads();
#pragma unroll
    for (int j = 0; j < 32; j += 8) {
        int n = n0 + ty + j, k = k0 + tx;
        if (n < Npad && k < Kpad)
            t[(size_t)n * Kpad + k] = __float2half(tile[tx][ty + j]);
    }
}

// ---------------------------------------------------------------------------
// exclusive scan of g_count -> g_offs
// ---------------------------------------------------------------------------
__global__ void scan_kernel() {
    __shared__ int part[1024];
    const int tid = threadIdx.x;
    const int CH = (NNODES + 1023) / 1024;
    const int base = tid * CH;
    int s = 0;
    for (int i = 0; i < CH; ++i) {
        int idx = base + i;
        if (idx < NNODES) s += g_count[idx];
    }
    part[tid] = s;
    __syncthreads();
    for (int off = 1; off < 1024; off <<= 1) {
        int v = (tid >= off) ? part[tid - off] : 0;
        __syncthreads();
        part[tid] += v;
        __syncthreads();
    }
    int run = part[tid] - s;
    for (int i = 0; i < CH; ++i) {
        int idx = base + i;
        if (idx < NNODES) { g_offs[idx] = run; run += g_count[idx]; }
    }
    if (tid == 1023) g_offs[NNODES] = part[1023];
}

__global__ void fill_kernel(const int* __restrict__ src, const int* __restrict__ dst) {
    int e = blockIdx.x * blockDim.x + threadIdx.x;
    if (e < NEDGES) {
        int d = dst[e];
        int p = atomicAdd(&g_pos[d], 1);
        g_eidx[g_offs[d] + p] = src[e];
    }
}

// ---------------------------------------------------------------------------
// HMMA GEMM (R7 configuration — frozen local optimum):
// CTA tile 128x128, 8 warps (4m x 2n), warp tile 32x64, 3-stage cp.async,
// BK=64, occupancy 2, per-tile grid.
// ---------------------------------------------------------------------------
#define BK 64
#define ROW_H 72                                // halves per smem row (64 + 8)
#define MAT_BYTES ((uint32_t)(128 * ROW_H * 2)) // 18432
#define B_OFF     MAT_BYTES
#define STAGE_BYTES (2 * MAT_BYTES)             // 36864
#define NSTAGE 3
#define GEMM_SMEM (NSTAGE * STAGE_BYTES)        // 110592

__global__ __launch_bounds__(256, 2)
void hmma_gemm_f16_kernel(const __half* __restrict__ a,
                          const __half* __restrict__ b,
                          __half* __restrict__ C,
                          int M, int Nreal, int Kpad) {
    extern __shared__ __half smem[];
    const uint32_t smem_u32 = smem_to_u32(smem);
    const int t = threadIdx.x;
    const int lane = t & 31;
    const int wid = t >> 5;
    const int wm = wid & 3;
    const int wn = wid >> 2;
    const int m0 = blockIdx.y * 128;
    const int n0 = blockIdx.x * 128;
    const int nchunk = Kpad / BK;

    float acc[2][8][4];
#pragma unroll
    for (int i = 0; i < 2; ++i)
#pragma unroll
        for (int j = 0; j < 8; ++j)
#pragma unroll
            for (int k = 0; k < 4; ++k) acc[i][j][k] = 0.f;

    auto load_stage = [&](int c) {
        const int slot = c % NSTAGE;
        const int k0 = c * BK;
        const uint32_t sbase = smem_u32 + slot * STAGE_BYTES;
#pragma unroll
        for (int i = 0; i < 4; ++i) {
            int idx = t + i * 256;
            int row = idx >> 3;
            int ch = idx & 7;
            uint32_t off = (uint32_t)(row * ROW_H + ch * 8) * 2;
            int gm = m0 + row;
            bool ok = gm < M;
            int gmc = ok ? gm : 0;
            size_t goa = (size_t)gmc * Kpad + k0 + ch * 8;
            cp_async16(sbase + off, a + goa, ok);
            size_t gob = (size_t)(n0 + row) * Kpad + k0 + ch * 8;
            cp_async16(sbase + off + B_OFF, b + gob, true);
        }
        CP_COMMIT();
    };

    load_stage(0);
    if (nchunk > 1) load_stage(1);

    for (int c = 0; c < nchunk; ++c) {
        if (c + 1 < nchunk) { CP_WAIT(1); } else { CP_WAIT(0); }
        __syncthreads();
        if (c + 2 < nchunk) load_stage(c + 2);

        const uint32_t sb = smem_u32 + (uint32_t)(c % NSTAGE) * STAGE_BYTES;
#pragma unroll
        for (int ks = 0; ks < 4; ++ks) {
            const int k0s = ks * 16;
            uint32_t af[2][4];
            {
                int ar = lane & 15;
                int ak = k0s + (lane >> 4) * 8;
#pragma unroll
                for (int mt = 0; mt < 2; ++mt) {
                    uint32_t addr = sb +
                        (uint32_t)((wm * 32 + mt * 16 + ar) * ROW_H + ak) * 2;
                    ldm_x4(af[mt][0], af[mt][1], af[mt][2], af[mt][3], addr);
                }
            }
            uint32_t bf[8][2];
            {
                int brr = (lane & 7) + (lane >> 4) * 8;
                int bk = k0s + ((lane >> 3) & 1) * 8;
#pragma unroll
                for (int ng = 0; ng < 4; ++ng) {
                    uint32_t addr = sb + B_OFF +
                        (uint32_t)((wn * 64 + ng * 16 + brr) * ROW_H + bk) * 2;
                    uint32_t r0, r1, r2, r3;
                    ldm_x4(r0, r1, r2, r3, addr);
                    bf[2 * ng][0] = r0; bf[2 * ng][1] = r1;
                    bf[2 * ng + 1][0] = r2; bf[2 * ng + 1][1] = r3;
                }
            }
#pragma unroll
            for (int mt = 0; mt < 2; ++mt) {
#pragma unroll
                for (int nt = 0; nt < 8; ++nt) {
                    mma_f16(acc[mt][nt], af[mt], bf[nt]);
                }
            }
        }
    }

    // epilogue: fp16 packed stores
#pragma unroll
    for (int mt = 0; mt < 2; ++mt) {
        int gr0 = m0 + wm * 32 + mt * 16 + (lane >> 2);
#pragma unroll
        for (int nt = 0; nt < 8; ++nt) {
            int gc = n0 + wn * 64 + nt * 8 + (lane & 3) * 2;
            if (gc >= Nreal) continue;
            if (gr0 < M) {
                *reinterpret_cast<uint32_t*>(&C[(size_t)gr0 * Nreal + gc]) =
                    pack_f16x2(acc[mt][nt][0], acc[mt][nt][1]);
            }
            if (gr0 + 8 < M) {
                *reinterpret_cast<uint32_t*>(&C[(size_t)(gr0 + 8) * Nreal + gc]) =
                    pack_f16x2(acc[mt][nt][2], acc[mt][nt][3]);
            }
        }
    }
}

// ---------------------------------------------------------------------------
// Aggregation 1: x1[i,:] = relu(b1 + sum_j t1[j,:]) -> fp16, padded to K2PAD
// ---------------------------------------------------------------------------
#define AGG1_NODES 4

__global__ __launch_bounds__(128)
void agg1_kernel(const __half* __restrict__ t,
                 const float* __restrict__ bias,
                 __half* __restrict__ x1) {
    const int tid = threadIdx.x;
    const int c = tid << 3;               // 0..1016
    const bool act = c < D_H1;            // threads 0..124
    float b[8];
    if (act) {
#pragma unroll
        for (int j = 0; j < 8; ++j) b[j] = bias[c + j];
    }
    const int node0 = blockIdx.x * AGG1_NODES;
#pragma unroll 1
    for (int ni = 0; ni < AGG1_NODES; ++ni) {
        const int node = node0 + ni;
        if (node >= NNODES) return;
        const int beg = g_offs[node], end = g_offs[node + 1];
        if (act) {
            float a[8];
#pragma unroll
            for (int j = 0; j < 8; ++j) a[j] = b[j];
            for (int e = beg; e < end; ++e) {
                const int s = g_eidx[e];   // warp-uniform -> L1 broadcast
                const uint4 v = *reinterpret_cast<const uint4*>(
                    t + (size_t)s * D_H1 + c);
                const __half2* h = reinterpret_cast<const __half2*>(&v);
#pragma unroll
                for (int j = 0; j < 4; ++j) {
                    float2 p = __half22float2(h[j]);
                    a[2 * j] += p.x;
                    a[2 * j + 1] += p.y;
                }
            }
            uint4 o;
            uint32_t* ow = reinterpret_cast<uint32_t*>(&o);
#pragma unroll
            for (int j = 0; j < 4; ++j)
                ow[j] = pack_f16x2(fmaxf(a[2 * j], 0.f), fmaxf(a[2 * j + 1], 0.f));
            *reinterpret_cast<uint4*>(x1 + (size_t)node * K2PAD + c) = o;
        } else {
            *reinterpret_cast<uint4*>(x1 + (size_t)node * K2PAD + c) =
                make_uint4(0u, 0u, 0u, 0u);
        }
    }
}

// ---------------------------------------------------------------------------
// Fused aggregation 2 + output layer + counter re-zero (for next call).
// ---------------------------------------------------------------------------
#define NODES_PER_CTA 8

__global__ __launch_bounds__(128)
void agg2_out_kernel(const __half* __restrict__ t,
                     const float* __restrict__ bias,
                     const float* __restrict__ W3,
                     const float* __restrict__ b3,
                     float* __restrict__ out) {
    __shared__ float Ws[D_H2 * D_OUT];          // 14 KB
    __shared__ float red[4][D_OUT];
    const int tid = threadIdx.x;
    const int lane = tid & 31;
    const int warp = tid >> 5;
    const int c = tid << 2;

    // re-zero CSR counters for the next invocation (invariant keeper)
    {
        int g = blockIdx.x * 128 + tid;
        if (g < NNODES) { g_count[g] = 0; g_pos[g] = 0; }
    }

    for (int i = tid; i < D_H2 * D_OUT; i += 128) Ws[i] = W3[i];
    float b0 = 0.f, b1v = 0.f, b2v = 0.f, b3v = 0.f;
    if (c < D_H2) {
        b0 = bias[c]; b1v = bias[c + 1]; b2v = bias[c + 2]; b3v = bias[c + 3];
    }
    __syncthreads();   // Ws visible

    const int node0 = blockIdx.x * NODES_PER_CTA;
#pragma unroll 1
    for (int ni = 0; ni < NODES_PER_CTA; ++ni) {
        const int node = node0 + ni;
        if (node >= NNODES) break;
        const int beg = g_offs[node], end = g_offs[node + 1];

        float p[D_OUT] = {0.f, 0.f, 0.f, 0.f, 0.f, 0.f, 0.f};
        if (c < D_H2) {
            float a0 = b0, a1 = b1v, a2 = b2v, a3 = b3v;
            for (int e = beg; e < end; ++e) {
                const int s = g_eidx[e];   // warp-uniform
                const half4 v = *reinterpret_cast<const half4*>(
                    t + (size_t)s * D_H2 + c);
                float2 q0 = __half22float2(v.a);
                float2 q1 = __half22float2(v.b);
                a0 += q0.x; a1 += q0.y; a2 += q1.x; a3 += q1.y;
            }
            a0 = fmaxf(a0, 0.f); a1 = fmaxf(a1, 0.f);
            a2 = fmaxf(a2, 0.f); a3 = fmaxf(a3, 0.f);
#pragma unroll
            for (int j = 0; j < D_OUT; ++j) {
                p[j] = a0 * Ws[(c + 0) * D_OUT + j]
                     + a1 * Ws[(c + 1) * D_OUT + j]
                     + a2 * Ws[(c + 2) * D_OUT + j]
                     + a3 * Ws[(c + 3) * D_OUT + j];
            }
        }
#pragma unroll
        for (int j = 0; j < D_OUT; ++j) {
#pragma unroll
            for (int off = 16; off > 0; off >>= 1)
                p[j] += __shfl_xor_sync(0xFFFFFFFFu, p[j], off);
        }
        if (lane == 0) {
#pragma unroll
            for (int j = 0; j < D_OUT; ++j) red[warp][j] = p[j];
        }
        __syncthreads();
        if (tid < D_OUT) {
            float s = red[0][tid] + red[1][tid] + red[2][tid] + red[3][tid];
            out[(size_t)node * D_OUT + tid] = fmaxf(s + b3[tid], 0.f);
        }
        __syncthreads();   // red reuse safety
    }
}

// ---------------------------------------------------------------------------
// Launch — two-stream fork/join (graph-capturable via event edges).
// Host-issue order: quantize(0) transpose(1) scan(2) gemm1(3=ncu slot)
//                   fill(4) agg1(5) gemm2(6) agg2_out(7)
// ---------------------------------------------------------------------------
extern "C" void kernel_launch(void* const* d_in, const int* in_sizes, int n_in,
                              void* d_out, int out_size) {
    const float* features = (const float*)d_in[0];
    const int*   src      = (const int*)  d_in[1];
    const int*   dst      = (const int*)  d_in[2];
    const float* W1       = (const float*)d_in[3];
    const float* b1       = (const float*)d_in[4];
    const float* W2       = (const float*)d_in[5];
    const float* b2       = (const float*)d_in[6];
    const float* W3       = (const float*)d_in[7];
    const float* b3       = (const float*)d_in[8];
    float* out = (float*)d_out;

    __half *fa, *w1t, *x1, *w2t, *t1, *t2;
    cudaGetSymbolAddress((void**)&fa, g_fa);
    cudaGetSymbolAddress((void**)&w1t, g_w1t);
    cudaGetSymbolAddress((void**)&x1, g_x1);
    cudaGetSymbolAddress((void**)&w2t, g_w2t);
    cudaGetSymbolAddress((void**)&t1, g_t1);
    cudaGetSymbolAddress((void**)&t2, g_t2);

    static cudaStream_t s2 = nullptr;
    static cudaEvent_t ev0 = nullptr, ev_q = nullptr, ev_t = nullptr, ev_f = nullptr;
    if (s2 == nullptr) {
        cudaStreamCreateWithFlags(&s2, cudaStreamNonBlocking);
        cudaEventCreateWithFlags(&ev0,  cudaEventDisableTiming);
        cudaEventCreateWithFlags(&ev_q, cudaEventDisableTiming);
        cudaEventCreateWithFlags(&ev_t, cudaEventDisableTiming);
        cudaEventCreateWithFlags(&ev_f, cudaEventDisableTiming);
        cudaFuncSetAttribute(hmma_gemm_f16_kernel,
                             cudaFuncAttributeMaxDynamicSharedMemorySize, GEMM_SMEM);
    }

    // fork: s2 joins the captured stream via origin event
    cudaEventRecord(ev0, 0);
    cudaStreamWaitEvent(s2, ev0, 0);

    // Launch 0 (s0): quantize features + CSR count (counters pre-zeroed)
    {
        size_t tot4 = (size_t)NNODES * (K1PAD / 4);
        quantize_count_kernel<<<(unsigned)((tot4 + 255) / 256), 256>>>(
            features, fa, dst, NNODES, D_IN, K1PAD);
    }
    cudaEventRecord(ev_q, 0);

    // Launch 1 (s2): both weight transposes (independent of s0 work)
    {
        dim3 tb(32, 8);
        dim3 tg(K1PAD / 32, N1PAD / 32, 2);
        transpose_both_kernel<<<tg, tb, 0, s2>>>(W1, w1t, W2, w2t);
    }
    cudaEventRecord(ev_t, s2);

    // Launch 2 (s2): CSR scan (needs count -> wait ev_q)
    cudaStreamWaitEvent(s2, ev_q, 0);
    scan_kernel<<<1, 1024, 0, s2>>>();

    // Launch 3 (s0, ncu capture slot): GEMM 1 (needs transposed W1 -> wait ev_t)
    cudaStreamWaitEvent(0, ev_t, 0);
    {
        dim3 grid(N1PAD / 128, (NNODES + 127) / 128);
        hmma_gemm_f16_kernel<<<grid, 256, GEMM_SMEM>>>(fa, w1t, t1,
                                                       NNODES, D_H1, K1PAD);
    }

    // Launch 4 (s2): CSR fill (after scan, in-stream) — overlaps gemm1
    fill_kernel<<<(NEDGES + 255) / 256, 256, 0, s2>>>(src, dst);
    cudaEventRecord(ev_f, s2);

    // join: agg1 needs gemm1 (s0 order) + fill (ev_f)
    cudaStreamWaitEvent(0, ev_f, 0);

    // Launch 5 (s0): layer-1 aggregation (4 nodes/CTA)
    {
        int blocks = (NNODES + AGG1_NODES - 1) / AGG1_NODES;
        agg1_kernel<<<blocks, 128>>>(t1, b1, x1);
    }

    // Launch 6 (s0): GEMM 2
    {
        dim3 grid(N2PAD / 128, (NNODES + 127) / 128);
        hmma_gemm_f16_kernel<<<grid, 256, GEMM_SMEM>>>(x1, w2t, t2,
                                                       NNODES, D_H2, K2PAD);
    }
    // Launch 7 (s0): fused aggregation 2 + output (+ counter re-zero)
    {
        int blocks = (NNODES + NODES_PER_CTA - 1) / NODES_PER_CTA;
        agg2_out_kernel<<<blocks, 128>>>(t2, b2, W3, b3, out);
    }
}